// round 10
// baseline (speedup 1.0000x reference)
#include <cuda_runtime.h>
#include <math.h>
#include <stdint.h>

// ---------------------------------------------------------------------------
// GCN 2-layer forward:
//   h1 = tanh( Anorm @ (x @ W1) + b1 )
//   h2 = tanh( Anorm @ (h1 @ W2) + b2 )
//
// R9: dinv[row] folded into the GEMM epilogue (hs[r] = (xW)[r]*dinv[r]), so
// Anorm@h = dinv[c]*(sum_{r in N(c)} hs[r] + hs[c]). The aggregate inner loop
// loses its per-edge random dinv gather (2.4M scalar L2 round-trips) and its
// per-edge FMAs. k_deg_zero removed (k_scan self-zeroes g_deg after reading).
// Launch order arranged so ncu's fixed sample point (#4) lands on k_mma.
//
// edge_index arrives as INT32 (JAX x64-disabled downcasts the int64 request).
// ---------------------------------------------------------------------------

#define NNODES_MAX 50000
#define NEDGES_MAX 800000
#define D_IN  256
#define D_H1  256
#define D_H2  128

__device__ float g_h[(size_t)NNODES_MAX * D_H1];    // buffer 1 (dinv-scaled GEMM out)
__device__ float g_agg[(size_t)NNODES_MAX * D_H1];  // buffer 2
__device__ float g_dinv[NNODES_MAX];

__device__ int g_deg[NNODES_MAX];        // zero-init at load; re-zeroed by k_scan
__device__ int g_start[NNODES_MAX + 1];
__device__ int g_cursor[NNODES_MAX];
__device__ int g_src[NEDGES_MAX];

template<int B> __device__ __forceinline__ float* buf() {
    return (B == 1) ? g_h : g_agg;
}

// Side stream + events (created pre-main; not device-memory allocations).
static cudaStream_t s_side = nullptr;
static cudaEvent_t  s_evFork = nullptr, s_evJoin = nullptr;
namespace {
struct StreamInit {
    StreamInit() {
        cudaStreamCreateWithFlags(&s_side, cudaStreamNonBlocking);
        cudaEventCreateWithFlags(&s_evFork, cudaEventDisableTiming);
        cudaEventCreateWithFlags(&s_evJoin, cudaEventDisableTiming);
    }
};
static StreamInit s_streamInit;
}

// ---------------------------- CSR build ------------------------------------

__global__ void k_deg_count(const int* __restrict__ col, int E) {
    int stride = gridDim.x * blockDim.x;
    for (int e = blockIdx.x * blockDim.x + threadIdx.x; e < E; e += stride)
        atomicAdd(&g_deg[col[e]], 1);
}

// Exclusive scan over g_deg -> g_start/g_cursor; computes dinv; RE-ZEROES
// g_deg so the next kernel_launch call (graph replay) starts clean.
__global__ __launch_bounds__(1024) void k_scan(int n) {
    __shared__ int part[1024];
    int t = threadIdx.x;
    int per = (n + 1023) / 1024;
    int base = t * per;

    int sum = 0;
    for (int i = 0; i < per; i++) {
        int idx = base + i;
        if (idx < n) sum += g_deg[idx];
    }
    part[t] = sum;
    __syncthreads();

    for (int off = 1; off < 1024; off <<= 1) {
        int v = (t >= off) ? part[t - off] : 0;
        __syncthreads();
        part[t] += v;
        __syncthreads();
    }

    int run = (t == 0) ? 0 : part[t - 1];
    for (int i = 0; i < per; i++) {
        int idx = base + i;
        if (idx < n) {
            int d = g_deg[idx];
            g_deg[idx] = 0;                        // restore for next replay
            g_start[idx] = run;
            g_cursor[idx] = run;
            g_dinv[idx] = rsqrtf((float)(d + 1));  // +1 self loop
            run += d;
        }
    }
    if (t == 0) g_start[n] = part[1023];
}

__global__ void k_csr_fill(const int* __restrict__ row, const int* __restrict__ col, int E) {
    int stride = gridDim.x * blockDim.x;
    for (int e = blockIdx.x * blockDim.x + threadIdx.x; e < E; e += stride) {
        int slot = atomicAdd(&g_cursor[col[e]], 1);
        g_src[slot] = row[e];
    }
}

// --------------------------- math helpers ----------------------------------

__device__ __forceinline__ uint32_t f2tf32(float f) {
    uint32_t u;
    asm("cvt.rna.tf32.f32 %0, %1;" : "=r"(u) : "f"(f));
    return u;
}

__device__ __forceinline__ float fast_tanh(float x) {
    float ax = fabsf(x);
    float t, r;
    asm("ex2.approx.f32 %0, %1;" : "=f"(t) : "f"(ax * -2.885390081777927f)); // -2*log2(e)
    asm("rcp.approx.f32 %0, %1;" : "=f"(r) : "f"(1.0f + t));
    float y = fmaf(-2.0f * t, r, 1.0f);
    return copysignf(y, x);
}

__device__ __forceinline__ void mma_tf32(
    float& c0, float& c1, float& c2, float& c3,
    uint32_t a0, uint32_t a1, uint32_t a2, uint32_t a3,
    uint32_t b0, uint32_t b1)
{
    asm volatile(
        "mma.sync.aligned.m16n8k8.row.col.f32.tf32.tf32.f32 "
        "{%0,%1,%2,%3}, {%4,%5,%6,%7}, {%8,%9}, {%0,%1,%2,%3};"
        : "+f"(c0), "+f"(c1), "+f"(c2), "+f"(c3)
        : "r"(a0), "r"(a1), "r"(a2), "r"(a3), "r"(b0), "r"(b1));
}

// -------------------------- tensor-core GEMM -------------------------------
// C[M,N] = (A[M,K] @ B[K,N]) * dinv[row]   (row scaling fused in epilogue)
// Block tile 128x128, BK=16. 8 warps (4M x 2N), warp tile 32x64.

#define A_STRIDE 20
#define B_STRIDE 136

template<int ASel, int DSel>
__global__ __launch_bounds__(256, 2) void k_mma(
    const float* __restrict__ Aext, const float* __restrict__ B,
    int M, int N, int K)
{
    const float* A = (ASel == 0) ? Aext : buf<ASel>();
    float* C = buf<DSel>();

    __shared__ uint32_t As[128 * A_STRIDE];
    __shared__ uint32_t Bs[16 * B_STRIDE];

    int tid  = threadIdx.x;
    int lane = tid & 31;
    int wid  = tid >> 5;
    int wm   = wid & 3;
    int wn   = wid >> 2;
    int bm   = blockIdx.x * 128;
    int bn   = blockIdx.y * 128;

    int aF0 = tid * 2, aF1 = tid * 2 + 1;
    int a_row0 = aF0 >> 2,        a_row1 = aF1 >> 2;
    int a_c0   = (aF0 & 3) * 4,   a_c1   = (aF1 & 3) * 4;
    int b_row0 = aF0 >> 5,        b_row1 = aF1 >> 5;
    int b_c0   = (aF0 & 31) * 4,  b_c1   = (aF1 & 31) * 4;

    float acc[2][8][4];
    #pragma unroll
    for (int i = 0; i < 2; i++)
        #pragma unroll
        for (int j = 0; j < 8; j++)
            #pragma unroll
            for (int v = 0; v < 4; v++) acc[i][j][v] = 0.0f;

    int lg = lane >> 2;
    int lq = lane & 3;

    float4 rA0, rA1, rB0, rB1;

    auto load_chunk = [&](int kc) {
        rA0 = make_float4(0.f, 0.f, 0.f, 0.f);
        rA1 = make_float4(0.f, 0.f, 0.f, 0.f);
        int gr0 = bm + a_row0, gr1 = bm + a_row1;
        if (gr0 < M) rA0 = *(const float4*)&A[(size_t)gr0 * K + kc + a_c0];
        if (gr1 < M) rA1 = *(const float4*)&A[(size_t)gr1 * K + kc + a_c1];
        rB0 = *(const float4*)&B[(size_t)(kc + b_row0) * N + bn + b_c0];
        rB1 = *(const float4*)&B[(size_t)(kc + b_row1) * N + bn + b_c1];
    };
    auto store_chunk = [&]() {
        uint4 t;
        t.x = f2tf32(rA0.x); t.y = f2tf32(rA0.y); t.z = f2tf32(rA0.z); t.w = f2tf32(rA0.w);
        *(uint4*)&As[a_row0 * A_STRIDE + a_c0] = t;
        t.x = f2tf32(rA1.x); t.y = f2tf32(rA1.y); t.z = f2tf32(rA1.z); t.w = f2tf32(rA1.w);
        *(uint4*)&As[a_row1 * A_STRIDE + a_c1] = t;
        t.x = f2tf32(rB0.x); t.y = f2tf32(rB0.y); t.z = f2tf32(rB0.z); t.w = f2tf32(rB0.w);
        *(uint4*)&Bs[b_row0 * B_STRIDE + b_c0] = t;
        t.x = f2tf32(rB1.x); t.y = f2tf32(rB1.y); t.z = f2tf32(rB1.z); t.w = f2tf32(rB1.w);
        *(uint4*)&Bs[b_row1 * B_STRIDE + b_c1] = t;
    };
    auto compute = [&]() {
        #pragma unroll
        for (int ks = 0; ks < 16; ks += 8) {
            uint32_t a[2][4];
            #pragma unroll
            for (int i = 0; i < 2; i++) {
                int r0 = wm * 32 + i * 16 + lg;
                a[i][0] = As[(r0    ) * A_STRIDE + ks + lq    ];
                a[i][1] = As[(r0 + 8) * A_STRIDE + ks + lq    ];
                a[i][2] = As[(r0    ) * A_STRIDE + ks + lq + 4];
                a[i][3] = As[(r0 + 8) * A_STRIDE + ks + lq + 4];
            }
            #pragma unroll
            for (int j = 0; j < 8; j++) {
                int cb = wn * 64 + j * 8 + lg;
                uint32_t b0 = Bs[(ks + lq    ) * B_STRIDE + cb];
                uint32_t b1 = Bs[(ks + lq + 4) * B_STRIDE + cb];
                #pragma unroll
                for (int i = 0; i < 2; i++)
                    mma_tf32(acc[i][j][0], acc[i][j][1], acc[i][j][2], acc[i][j][3],
                             a[i][0], a[i][1], a[i][2], a[i][3], b0, b1);
            }
        }
    };

    load_chunk(0);
    store_chunk();
    __syncthreads();

    for (int kc = 16; kc < K; kc += 16) {
        load_chunk(kc);
        compute();
        __syncthreads();
        store_chunk();
        __syncthreads();
    }
    compute();

    // epilogue: scale each output row by dinv[row] (hs = h * dinv)
    #pragma unroll
    for (int i = 0; i < 2; i++) {
        int row0 = bm + wm * 32 + i * 16 + lg;
        int row1 = row0 + 8;
        float s0 = (row0 < M) ? g_dinv[row0] : 0.f;
        float s1 = (row1 < M) ? g_dinv[row1] : 0.f;
        #pragma unroll
        for (int j = 0; j < 8; j++) {
            int colb = bn + wn * 64 + j * 8 + 2 * lq;
            if (row0 < M)
                *(float2*)&C[(size_t)row0 * N + colb] =
                    make_float2(acc[i][j][0] * s0, acc[i][j][1] * s0);
            if (row1 < M)
                *(float2*)&C[(size_t)row1 * N + colb] =
                    make_float2(acc[i][j][2] * s1, acc[i][j][3] * s1);
        }
    }
}

// ---------------------- fused CSR aggregation ------------------------------
// Input hs = (XW)*dinv (row-scaled in GEMM epilogue). One warp per
// (node, 128-col segment):
//   out[c,seg] = tanh( dinv[c]*( sum_{r in N(c)} hs[r,seg] + hs[c,seg] ) + bias )
// Inner loop: broadcast index, one 128B gather, 4 FADD. No weight loads.

template<int D, int NSEG, int HSel, int OSel>
__global__ __launch_bounds__(256) void k_aggregate(
    const float* __restrict__ bias, float* __restrict__ outext, int n)
{
    const float* h = buf<HSel>();
    float* out = (OSel == 0) ? outext : buf<OSel>();

    int gwarp = (int)((blockIdx.x * (unsigned)blockDim.x + threadIdx.x) >> 5);
    int lane = threadIdx.x & 31;
    int node = gwarp / NSEG;
    int seg  = gwarp % NSEG;
    if (node >= n) return;

    int off = seg * 128 + lane * 4;

    float4 acc = make_float4(0.f, 0.f, 0.f, 0.f);

    int beg = g_start[node];
    int end = g_start[node + 1];

    int e = beg;
    for (; e + 4 <= end; e += 4) {
        int r0 = g_src[e];
        int r1 = g_src[e + 1];
        int r2 = g_src[e + 2];
        int r3 = g_src[e + 3];
        float4 v0 = *(const float4*)&h[(size_t)r0 * D + off];
        float4 v1 = *(const float4*)&h[(size_t)r1 * D + off];
        float4 v2 = *(const float4*)&h[(size_t)r2 * D + off];
        float4 v3 = *(const float4*)&h[(size_t)r3 * D + off];
        acc.x += v0.x; acc.y += v0.y; acc.z += v0.z; acc.w += v0.w;
        acc.x += v1.x; acc.y += v1.y; acc.z += v1.z; acc.w += v1.w;
        acc.x += v2.x; acc.y += v2.y; acc.z += v2.z; acc.w += v2.w;
        acc.x += v3.x; acc.y += v3.y; acc.z += v3.z; acc.w += v3.w;
    }
    for (; e < end; e++) {
        int r = g_src[e];
        float4 v = *(const float4*)&h[(size_t)r * D + off];
        acc.x += v.x; acc.y += v.y; acc.z += v.z; acc.w += v.w;
    }

    float dc = g_dinv[node];
    float4 hv = *(const float4*)&h[(size_t)node * D + off];   // hs[c] (scaled)
    float4 bv = *(const float4*)&bias[off];
    float4 o;
    o.x = fast_tanh(fmaf(dc, acc.x + hv.x, bv.x));
    o.y = fast_tanh(fmaf(dc, acc.y + hv.y, bv.y));
    o.z = fast_tanh(fmaf(dc, acc.z + hv.z, bv.z));
    o.w = fast_tanh(fmaf(dc, acc.w + hv.w, bv.w));
    *(float4*)&out[(size_t)node * D + off] = o;
}

// ------------------------------ launch -------------------------------------

extern "C" void kernel_launch(void* const* d_in, const int* in_sizes, int n_in,
                              void* d_out, int out_size)
{
    const float* x   = (const float*)d_in[0];
    const int*   ei  = (const int*)d_in[1];     // int32 (JAX x64-disabled)
    const float* W1  = (const float*)d_in[2];
    const float* b1  = (const float*)d_in[3];
    const float* W2  = (const float*)d_in[4];
    const float* b2  = (const float*)d_in[5];
    float*       out = (float*)d_out;

    int n = in_sizes[0] / D_IN;       // 50000
    int E = in_sizes[1] / 2;          // 800000
    const int* row = ei;
    const int* col = ei + E;

    // (1) deg count + scan on main (mma1 epilogue needs dinv)
    k_deg_count<<<1024, 256>>>(col, E);          // launch 1
    k_scan<<<1, 1024>>>(n);                      // launch 2

    // (2) fork: csr_fill on side stream, overlapping mma1
    cudaEventRecord(s_evFork, 0);
    cudaStreamWaitEvent(s_side, s_evFork, 0);
    k_csr_fill<<<1024, 256, 0, s_side>>>(row, col, E);   // launch 3
    cudaEventRecord(s_evJoin, s_side);

    {   // layer 1 GEMM: g_h = (x @ W1) * dinv[row]     // launch 4 (ncu target)
        dim3 grid((n + 127) / 128, D_H1 / 128);
        k_mma<0, 1><<<grid, 256>>>(x, W1, n, D_H1, D_IN);
    }

    cudaStreamWaitEvent(0, s_evJoin, 0);   // aggregate needs CSR fill

    // ---- layer 1 aggregate: g_agg = tanh(dinv*(sum hs + hs_self) + b1) ----
    {
        int warps = n * (D_H1 / 128);
        k_aggregate<D_H1, D_H1 / 128, 1, 2><<<(warps + 7) / 8, 256>>>(b1, nullptr, n);
    }

    // ---- layer 2 ----
    {
        dim3 grid((n + 127) / 128, D_H2 / 128);
        k_mma<2, 1><<<grid, 256>>>(nullptr, W2, n, D_H2, D_H1);
        int warps = n * (D_H2 / 128);
        k_aggregate<D_H2, D_H2 / 128, 1, 0><<<(warps + 7) / 8, 256>>>(b2, out, n);
    }
}

// round 11
// speedup vs baseline: 1.0585x; 1.0585x over previous
#include <cuda_runtime.h>
#include <cuda_fp16.h>
#include <math.h>
#include <stdint.h>

// ---------------------------------------------------------------------------
// GCN 2-layer forward:
//   h1 = tanh( Anorm @ (x @ W1) + b1 )
//   h2 = tanh( Anorm @ (h1 @ W2) + b2 )
//
// R10: aggregates are L2-BANDWIDTH-bound (full 1KB/512B row gathered per
// edge => ~1.4GB through LTS; explains why R7-R9 latency tweaks were flat).
// Fix: GEMM epilogues emit h in FP16 -> gather traffic halved. Aggregate
// outputs stay fp32 (GEMM inputs unchanged). dinv fold reverted (it forced
// deg_count+scan serial before GEMM1 = R9's +21us); CSR chain fully
// overlapped under GEMM1 again.
//
// edge_index arrives as INT32 (JAX x64-disabled downcasts the int64 request).
// ---------------------------------------------------------------------------

#define NNODES_MAX 50000
#define NEDGES_MAX 800000
#define D_IN  256
#define D_H1  256
#define D_H2  128

__device__ __half g_hh[(size_t)NNODES_MAX * D_H1];  // fp16 GEMM output (h)
__device__ float  g_agg[(size_t)NNODES_MAX * D_H1]; // fp32 aggregate output
__device__ float  g_dinv[NNODES_MAX];

__device__ int g_deg[NNODES_MAX];        // zero at load; re-zeroed by k_scan
__device__ int g_start[NNODES_MAX + 1];
__device__ int g_cursor[NNODES_MAX];
__device__ int g_src[NEDGES_MAX];

// Side stream + events (created pre-main; not device-memory allocations).
static cudaStream_t s_side = nullptr;
static cudaEvent_t  s_evFork = nullptr, s_evJoin = nullptr;
namespace {
struct StreamInit {
    StreamInit() {
        cudaStreamCreateWithFlags(&s_side, cudaStreamNonBlocking);
        cudaEventCreateWithFlags(&s_evFork, cudaEventDisableTiming);
        cudaEventCreateWithFlags(&s_evJoin, cudaEventDisableTiming);
    }
};
static StreamInit s_streamInit;
}

// ---------------------------- CSR build ------------------------------------

__global__ void k_deg_count(const int* __restrict__ col, int E) {
    int stride = gridDim.x * blockDim.x;
    for (int e = blockIdx.x * blockDim.x + threadIdx.x; e < E; e += stride)
        atomicAdd(&g_deg[col[e]], 1);
}

// Scan g_deg -> g_start/g_cursor; dinv; re-zero g_deg for the next replay.
__global__ __launch_bounds__(1024) void k_scan(int n) {
    __shared__ int part[1024];
    int t = threadIdx.x;
    int per = (n + 1023) / 1024;
    int base = t * per;

    int sum = 0;
    for (int i = 0; i < per; i++) {
        int idx = base + i;
        if (idx < n) sum += g_deg[idx];
    }
    part[t] = sum;
    __syncthreads();

    for (int off = 1; off < 1024; off <<= 1) {
        int v = (t >= off) ? part[t - off] : 0;
        __syncthreads();
        part[t] += v;
        __syncthreads();
    }

    int run = (t == 0) ? 0 : part[t - 1];
    for (int i = 0; i < per; i++) {
        int idx = base + i;
        if (idx < n) {
            int d = g_deg[idx];
            g_deg[idx] = 0;
            g_start[idx] = run;
            g_cursor[idx] = run;
            g_dinv[idx] = rsqrtf((float)(d + 1));  // +1 self loop
            run += d;
        }
    }
    if (t == 0) g_start[n] = part[1023];
}

__global__ void k_csr_fill(const int* __restrict__ row, const int* __restrict__ col, int E) {
    int stride = gridDim.x * blockDim.x;
    for (int e = blockIdx.x * blockDim.x + threadIdx.x; e < E; e += stride) {
        int slot = atomicAdd(&g_cursor[col[e]], 1);
        g_src[slot] = row[e];
    }
}

// --------------------------- math helpers ----------------------------------

__device__ __forceinline__ uint32_t f2tf32(float f) {
    uint32_t u;
    asm("cvt.rna.tf32.f32 %0, %1;" : "=r"(u) : "f"(f));
    return u;
}

__device__ __forceinline__ float fast_tanh(float x) {
    float ax = fabsf(x);
    float t, r;
    asm("ex2.approx.f32 %0, %1;" : "=f"(t) : "f"(ax * -2.885390081777927f)); // -2*log2(e)
    asm("rcp.approx.f32 %0, %1;" : "=f"(r) : "f"(1.0f + t));
    float y = fmaf(-2.0f * t, r, 1.0f);
    return copysignf(y, x);
}

__device__ __forceinline__ void mma_tf32(
    float& c0, float& c1, float& c2, float& c3,
    uint32_t a0, uint32_t a1, uint32_t a2, uint32_t a3,
    uint32_t b0, uint32_t b1)
{
    asm volatile(
        "mma.sync.aligned.m16n8k8.row.col.f32.tf32.tf32.f32 "
        "{%0,%1,%2,%3}, {%4,%5,%6,%7}, {%8,%9}, {%0,%1,%2,%3};"
        : "+f"(c0), "+f"(c1), "+f"(c2), "+f"(c3)
        : "r"(a0), "r"(a1), "r"(a2), "r"(a3), "r"(b0), "r"(b1));
}

// -------------------------- tensor-core GEMM -------------------------------
// g_hh[M,N] (fp16) = A[M,K] (fp32) @ B[K,N] (fp32), tf32 mma / f32 accum.
// Block tile 128x128, BK=16, 8 warps (4M x 2N), warp tile 32x64.
// ASel: 0 -> Aext param, 2 -> g_agg.

#define A_STRIDE 20
#define B_STRIDE 136

template<int ASel>
__global__ __launch_bounds__(256, 2) void k_mma(
    const float* __restrict__ Aext, const float* __restrict__ B,
    int M, int N, int K)
{
    const float* A = (ASel == 0) ? Aext : g_agg;
    __half* C = g_hh;

    __shared__ uint32_t As[128 * A_STRIDE];
    __shared__ uint32_t Bs[16 * B_STRIDE];

    int tid  = threadIdx.x;
    int lane = tid & 31;
    int wid  = tid >> 5;
    int wm   = wid & 3;
    int wn   = wid >> 2;
    int bm   = blockIdx.x * 128;
    int bn   = blockIdx.y * 128;

    int aF0 = tid * 2, aF1 = tid * 2 + 1;
    int a_row0 = aF0 >> 2,        a_row1 = aF1 >> 2;
    int a_c0   = (aF0 & 3) * 4,   a_c1   = (aF1 & 3) * 4;
    int b_row0 = aF0 >> 5,        b_row1 = aF1 >> 5;
    int b_c0   = (aF0 & 31) * 4,  b_c1   = (aF1 & 31) * 4;

    float acc[2][8][4];
    #pragma unroll
    for (int i = 0; i < 2; i++)
        #pragma unroll
        for (int j = 0; j < 8; j++)
            #pragma unroll
            for (int v = 0; v < 4; v++) acc[i][j][v] = 0.0f;

    int lg = lane >> 2;
    int lq = lane & 3;

    float4 rA0, rA1, rB0, rB1;

    auto load_chunk = [&](int kc) {
        rA0 = make_float4(0.f, 0.f, 0.f, 0.f);
        rA1 = make_float4(0.f, 0.f, 0.f, 0.f);
        int gr0 = bm + a_row0, gr1 = bm + a_row1;
        if (gr0 < M) rA0 = *(const float4*)&A[(size_t)gr0 * K + kc + a_c0];
        if (gr1 < M) rA1 = *(const float4*)&A[(size_t)gr1 * K + kc + a_c1];
        rB0 = *(const float4*)&B[(size_t)(kc + b_row0) * N + bn + b_c0];
        rB1 = *(const float4*)&B[(size_t)(kc + b_row1) * N + bn + b_c1];
    };
    auto store_chunk = [&]() {
        uint4 t;
        t.x = f2tf32(rA0.x); t.y = f2tf32(rA0.y); t.z = f2tf32(rA0.z); t.w = f2tf32(rA0.w);
        *(uint4*)&As[a_row0 * A_STRIDE + a_c0] = t;
        t.x = f2tf32(rA1.x); t.y = f2tf32(rA1.y); t.z = f2tf32(rA1.z); t.w = f2tf32(rA1.w);
        *(uint4*)&As[a_row1 * A_STRIDE + a_c1] = t;
        t.x = f2tf32(rB0.x); t.y = f2tf32(rB0.y); t.z = f2tf32(rB0.z); t.w = f2tf32(rB0.w);
        *(uint4*)&Bs[b_row0 * B_STRIDE + b_c0] = t;
        t.x = f2tf32(rB1.x); t.y = f2tf32(rB1.y); t.z = f2tf32(rB1.z); t.w = f2tf32(rB1.w);
        *(uint4*)&Bs[b_row1 * B_STRIDE + b_c1] = t;
    };
    auto compute = [&]() {
        #pragma unroll
        for (int ks = 0; ks < 16; ks += 8) {
            uint32_t a[2][4];
            #pragma unroll
            for (int i = 0; i < 2; i++) {
                int r0 = wm * 32 + i * 16 + lg;
                a[i][0] = As[(r0    ) * A_STRIDE + ks + lq    ];
                a[i][1] = As[(r0 + 8) * A_STRIDE + ks + lq    ];
                a[i][2] = As[(r0    ) * A_STRIDE + ks + lq + 4];
                a[i][3] = As[(r0 + 8) * A_STRIDE + ks + lq + 4];
            }
            #pragma unroll
            for (int j = 0; j < 8; j++) {
                int cb = wn * 64 + j * 8 + lg;
                uint32_t b0 = Bs[(ks + lq    ) * B_STRIDE + cb];
                uint32_t b1 = Bs[(ks + lq + 4) * B_STRIDE + cb];
                #pragma unroll
                for (int i = 0; i < 2; i++)
                    mma_tf32(acc[i][j][0], acc[i][j][1], acc[i][j][2], acc[i][j][3],
                             a[i][0], a[i][1], a[i][2], a[i][3], b0, b1);
            }
        }
    };

    load_chunk(0);
    store_chunk();
    __syncthreads();

    for (int kc = 16; kc < K; kc += 16) {
        load_chunk(kc);
        compute();
        __syncthreads();
        store_chunk();
        __syncthreads();
    }
    compute();

    // epilogue: write fp16
    #pragma unroll
    for (int i = 0; i < 2; i++) {
        int row0 = bm + wm * 32 + i * 16 + lg;
        int row1 = row0 + 8;
        #pragma unroll
        for (int j = 0; j < 8; j++) {
            int colb = bn + wn * 64 + j * 8 + 2 * lq;
            if (row0 < M)
                *(__half2*)&C[(size_t)row0 * N + colb] =
                    __floats2half2_rn(acc[i][j][0], acc[i][j][1]);
            if (row1 < M)
                *(__half2*)&C[(size_t)row1 * N + colb] =
                    __floats2half2_rn(acc[i][j][2], acc[i][j][3]);
        }
    }
}

// ---------------------- fused CSR aggregation ------------------------------
// out[c,:] = tanh( dinv[c]*( sum_r dinv[r]*h[r,:] + dinv[c]*h[c,:] ) + bias )
// h in fp16 (g_hh). One warp per node.

// Layer 1: D=256. Lane covers 8 cols (uint4 = 8 halves). Output fp32 g_agg.
__global__ __launch_bounds__(256) void k_agg1(const float* __restrict__ bias, int n)
{
    int node = (int)((blockIdx.x * (unsigned)blockDim.x + threadIdx.x) >> 5);
    int lane = threadIdx.x & 31;
    if (node >= n) return;
    int base = lane * 8;

    float acc[8];
    #pragma unroll
    for (int k = 0; k < 8; k++) acc[k] = 0.f;

    int beg = g_start[node];
    int end = g_start[node + 1];

    int e = beg;
    for (; e + 2 <= end; e += 2) {
        int r0 = g_src[e];
        int r1 = g_src[e + 1];
        float w0 = __ldg(&g_dinv[r0]);
        float w1 = __ldg(&g_dinv[r1]);
        uint4 p0 = *(const uint4*)&g_hh[(size_t)r0 * D_H1 + base];
        uint4 p1 = *(const uint4*)&g_hh[(size_t)r1 * D_H1 + base];
        const __half2* q0 = (const __half2*)&p0;
        const __half2* q1 = (const __half2*)&p1;
        #pragma unroll
        for (int k = 0; k < 4; k++) {
            float2 f0 = __half22float2(q0[k]);
            float2 f1 = __half22float2(q1[k]);
            acc[2*k]   = fmaf(w0, f0.x, fmaf(w1, f1.x, acc[2*k]));
            acc[2*k+1] = fmaf(w0, f0.y, fmaf(w1, f1.y, acc[2*k+1]));
        }
    }
    if (e < end) {
        int r = g_src[e];
        float w = __ldg(&g_dinv[r]);
        uint4 p = *(const uint4*)&g_hh[(size_t)r * D_H1 + base];
        const __half2* q = (const __half2*)&p;
        #pragma unroll
        for (int k = 0; k < 4; k++) {
            float2 f = __half22float2(q[k]);
            acc[2*k]   = fmaf(w, f.x, acc[2*k]);
            acc[2*k+1] = fmaf(w, f.y, acc[2*k+1]);
        }
    }

    float dc = g_dinv[node];
    {   // self loop (weight dc)
        uint4 p = *(const uint4*)&g_hh[(size_t)node * D_H1 + base];
        const __half2* q = (const __half2*)&p;
        #pragma unroll
        for (int k = 0; k < 4; k++) {
            float2 f = __half22float2(q[k]);
            acc[2*k]   = fmaf(dc, f.x, acc[2*k]);
            acc[2*k+1] = fmaf(dc, f.y, acc[2*k+1]);
        }
    }

    float4 bv0 = *(const float4*)&bias[base];
    float4 bv1 = *(const float4*)&bias[base + 4];
    float4 o0, o1;
    o0.x = fast_tanh(fmaf(dc, acc[0], bv0.x));
    o0.y = fast_tanh(fmaf(dc, acc[1], bv0.y));
    o0.z = fast_tanh(fmaf(dc, acc[2], bv0.z));
    o0.w = fast_tanh(fmaf(dc, acc[3], bv0.w));
    o1.x = fast_tanh(fmaf(dc, acc[4], bv1.x));
    o1.y = fast_tanh(fmaf(dc, acc[5], bv1.y));
    o1.z = fast_tanh(fmaf(dc, acc[6], bv1.z));
    o1.w = fast_tanh(fmaf(dc, acc[7], bv1.w));
    *(float4*)&g_agg[(size_t)node * D_H1 + base] = o0;
    *(float4*)&g_agg[(size_t)node * D_H1 + base + 4] = o1;
}

// Layer 2: D=128. Lane covers 4 cols (uint2 = 4 halves). Output fp32 outext.
__global__ __launch_bounds__(256) void k_agg2(
    const float* __restrict__ bias, float* __restrict__ out, int n)
{
    int node = (int)((blockIdx.x * (unsigned)blockDim.x + threadIdx.x) >> 5);
    int lane = threadIdx.x & 31;
    if (node >= n) return;
    int base = lane * 4;

    float acc[4];
    #pragma unroll
    for (int k = 0; k < 4; k++) acc[k] = 0.f;

    int beg = g_start[node];
    int end = g_start[node + 1];

    int e = beg;
    for (; e + 4 <= end; e += 4) {
        int r0 = g_src[e],     r1 = g_src[e + 1];
        int r2 = g_src[e + 2], r3 = g_src[e + 3];
        float w0 = __ldg(&g_dinv[r0]);
        float w1 = __ldg(&g_dinv[r1]);
        float w2 = __ldg(&g_dinv[r2]);
        float w3 = __ldg(&g_dinv[r3]);
        uint2 p0 = *(const uint2*)&g_hh[(size_t)r0 * D_H2 + base];
        uint2 p1 = *(const uint2*)&g_hh[(size_t)r1 * D_H2 + base];
        uint2 p2 = *(const uint2*)&g_hh[(size_t)r2 * D_H2 + base];
        uint2 p3 = *(const uint2*)&g_hh[(size_t)r3 * D_H2 + base];
        const __half2* q0 = (const __half2*)&p0;
        const __half2* q1 = (const __half2*)&p1;
        const __half2* q2 = (const __half2*)&p2;
        const __half2* q3 = (const __half2*)&p3;
        #pragma unroll
        for (int k = 0; k < 2; k++) {
            float2 f0 = __half22float2(q0[k]);
            float2 f1 = __half22float2(q1[k]);
            float2 f2 = __half22float2(q2[k]);
            float2 f3 = __half22float2(q3[k]);
            acc[2*k]   = fmaf(w0, f0.x, fmaf(w1, f1.x, fmaf(w2, f2.x, fmaf(w3, f3.x, acc[2*k]))));
            acc[2*k+1] = fmaf(w0, f0.y, fmaf(w1, f1.y, fmaf(w2, f2.y, fmaf(w3, f3.y, acc[2*k+1]))));
        }
    }
    for (; e < end; e++) {
        int r = g_src[e];
        float w = __ldg(&g_dinv[r]);
        uint2 p = *(const uint2*)&g_hh[(size_t)r * D_H2 + base];
        const __half2* q = (const __half2*)&p;
        #pragma unroll
        for (int k = 0; k < 2; k++) {
            float2 f = __half22float2(q[k]);
            acc[2*k]   = fmaf(w, f.x, acc[2*k]);
            acc[2*k+1] = fmaf(w, f.y, acc[2*k+1]);
        }
    }

    float dc = g_dinv[node];
    {
        uint2 p = *(const uint2*)&g_hh[(size_t)node * D_H2 + base];
        const __half2* q = (const __half2*)&p;
        #pragma unroll
        for (int k = 0; k < 2; k++) {
            float2 f = __half22float2(q[k]);
            acc[2*k]   = fmaf(dc, f.x, acc[2*k]);
            acc[2*k+1] = fmaf(dc, f.y, acc[2*k+1]);
        }
    }

    float4 bv = *(const float4*)&bias[base];
    float4 o;
    o.x = fast_tanh(fmaf(dc, acc[0], bv.x));
    o.y = fast_tanh(fmaf(dc, acc[1], bv.y));
    o.z = fast_tanh(fmaf(dc, acc[2], bv.z));
    o.w = fast_tanh(fmaf(dc, acc[3], bv.w));
    *(float4*)&out[(size_t)node * D_H2 + base] = o;
}

// ------------------------------ launch -------------------------------------

extern "C" void kernel_launch(void* const* d_in, const int* in_sizes, int n_in,
                              void* d_out, int out_size)
{
    const float* x   = (const float*)d_in[0];
    const int*   ei  = (const int*)d_in[1];     // int32 (JAX x64-disabled)
    const float* W1  = (const float*)d_in[2];
    const float* b1  = (const float*)d_in[3];
    const float* W2  = (const float*)d_in[4];
    const float* b2  = (const float*)d_in[5];
    float*       out = (float*)d_out;

    int n = in_sizes[0] / D_IN;       // 50000
    int E = in_sizes[1] / 2;          // 800000
    const int* row = ei;
    const int* col = ei + E;

    // fork: full CSR chain on side stream, overlapping GEMM1 (independent)
    cudaEventRecord(s_evFork, 0);
    cudaStreamWaitEvent(s_side, s_evFork, 0);
    k_deg_count<<<1024, 256, 0, s_side>>>(col, E);   // launch 1
    k_scan<<<1, 1024, 0, s_side>>>(n);               // launch 2
    k_csr_fill<<<1024, 256, 0, s_side>>>(row, col, E); // launch 3
    cudaEventRecord(s_evJoin, s_side);

    {   // layer 1 GEMM: g_hh = fp16(x @ W1)          // launch 4 (ncu slot)
        dim3 grid((n + 127) / 128, D_H1 / 128);
        k_mma<0><<<grid, 256>>>(x, W1, n, D_H1, D_IN);
    }

    cudaStreamWaitEvent(0, s_evJoin, 0);   // aggregate needs CSR + dinv

    // layer 1 aggregate: g_agg = tanh(...)  (fp32 out for GEMM2)
    k_agg1<<<(n * 32 + 255) / 256, 256>>>(b1, n);

    // layer 2 GEMM: g_hh = fp16(g_agg @ W2)
    {
        dim3 grid((n + 127) / 128, D_H2 / 128);
        k_mma<2><<<grid, 256>>>(nullptr, W2, n, D_H2, D_H1);
    }

    // layer 2 aggregate: out = tanh(...)
    k_agg2<<<(n * 32 + 255) / 256, 256>>>(b2, out, n);
}

// round 12
// speedup vs baseline: 1.7447x; 1.6482x over previous
#include <cuda_runtime.h>
#include <cuda_fp16.h>
#include <math.h>
#include <stdint.h>

// ---------------------------------------------------------------------------
// GCN 2-layer forward:
//   h1 = tanh( Anorm @ (x @ W1) + b1 )
//   h2 = tanh( Anorm @ (h1 @ W2) + b2 )
//
// R11: the single-block k_scan (~100us on one SM!) was the hidden critical
// path of the "overlapped" CSR build (fits R8/R9/R10 totals within a few us).
// Replaced by a 3-kernel multi-block scan (~10us): partial sums -> scan of
// partials -> apply. CSR chain now ~45us, genuinely hidden under GEMM1.
// GEMM (tf32->fp16 out) and aggregates (fp16 gather) unchanged from R10.
//
// edge_index arrives as INT32 (JAX x64-disabled downcasts the int64 request).
// ---------------------------------------------------------------------------

#define NNODES_MAX 50000
#define NEDGES_MAX 800000
#define D_IN  256
#define D_H1  256
#define D_H2  128

__device__ __half g_hh[(size_t)NNODES_MAX * D_H1];  // fp16 GEMM output (h)
__device__ float  g_agg[(size_t)NNODES_MAX * D_H1]; // fp32 aggregate output
__device__ float  g_dinv[NNODES_MAX];

__device__ int g_deg[NNODES_MAX];        // zero at load; re-zeroed by k_apply
__device__ int g_start[NNODES_MAX + 1];
__device__ int g_cursor[NNODES_MAX];
__device__ int g_src[NEDGES_MAX];

#define SCAN_T 256
#define SCAN_NB ((NNODES_MAX + SCAN_T - 1) / SCAN_T)   // 196
__device__ int g_part[SCAN_NB];
__device__ int g_partpref[SCAN_NB];

// Side stream + events (created pre-main; not device-memory allocations).
static cudaStream_t s_side = nullptr;
static cudaEvent_t  s_evFork = nullptr, s_evJoin = nullptr;
namespace {
struct StreamInit {
    StreamInit() {
        cudaStreamCreateWithFlags(&s_side, cudaStreamNonBlocking);
        cudaEventCreateWithFlags(&s_evFork, cudaEventDisableTiming);
        cudaEventCreateWithFlags(&s_evJoin, cudaEventDisableTiming);
    }
};
static StreamInit s_streamInit;
}

// ---------------------------- CSR build ------------------------------------

__global__ void k_deg_count(const int* __restrict__ col, int E) {
    int stride = gridDim.x * blockDim.x;
    for (int e = blockIdx.x * blockDim.x + threadIdx.x; e < E; e += stride)
        atomicAdd(&g_deg[col[e]], 1);
}

// (1) per-block partial sums of g_deg
__global__ __launch_bounds__(SCAN_T) void k_partial(int n) {
    __shared__ int s[SCAN_T];
    int t = threadIdx.x;
    int i = blockIdx.x * SCAN_T + t;
    s[t] = (i < n) ? g_deg[i] : 0;
    __syncthreads();
    #pragma unroll
    for (int off = SCAN_T / 2; off > 0; off >>= 1) {
        if (t < off) s[t] += s[t + off];
        __syncthreads();
    }
    if (t == 0) g_part[blockIdx.x] = s[0];
}

// (2) exclusive scan of the block partials (single tiny block)
__global__ __launch_bounds__(SCAN_T) void k_scanpart(int nb) {
    __shared__ int s[SCAN_T];
    int t = threadIdx.x;
    int my = (t < nb) ? g_part[t] : 0;
    s[t] = my;
    __syncthreads();
    #pragma unroll
    for (int off = 1; off < SCAN_T; off <<= 1) {
        int v = (t >= off) ? s[t - off] : 0;
        __syncthreads();
        s[t] += v;
        __syncthreads();
    }
    if (t < nb) g_partpref[t] = s[t] - my;   // exclusive
}

// (3) block-local scan + global offset; writes start/cursor/dinv; re-zeroes deg
__global__ __launch_bounds__(SCAN_T) void k_apply(int n) {
    __shared__ int s[SCAN_T];
    int t = threadIdx.x;
    int i = blockIdx.x * SCAN_T + t;
    int d = (i < n) ? g_deg[i] : 0;
    s[t] = d;
    __syncthreads();
    #pragma unroll
    for (int off = 1; off < SCAN_T; off <<= 1) {
        int v = (t >= off) ? s[t - off] : 0;
        __syncthreads();
        s[t] += v;
        __syncthreads();
    }
    int ex = s[t] - d + g_partpref[blockIdx.x];
    if (i < n) {
        g_deg[i] = 0;                          // restore for next graph replay
        g_start[i] = ex;
        g_cursor[i] = ex;
        g_dinv[i] = rsqrtf((float)(d + 1));    // +1 self loop
        if (i == n - 1) g_start[n] = ex + d;
    }
}

__global__ void k_csr_fill(const int* __restrict__ row, const int* __restrict__ col, int E) {
    int stride = gridDim.x * blockDim.x;
    for (int e = blockIdx.x * blockDim.x + threadIdx.x; e < E; e += stride) {
        int slot = atomicAdd(&g_cursor[col[e]], 1);
        g_src[slot] = row[e];
    }
}

// --------------------------- math helpers ----------------------------------

__device__ __forceinline__ uint32_t f2tf32(float f) {
    uint32_t u;
    asm("cvt.rna.tf32.f32 %0, %1;" : "=r"(u) : "f"(f));
    return u;
}

__device__ __forceinline__ float fast_tanh(float x) {
    float ax = fabsf(x);
    float t, r;
    asm("ex2.approx.f32 %0, %1;" : "=f"(t) : "f"(ax * -2.885390081777927f)); // -2*log2(e)
    asm("rcp.approx.f32 %0, %1;" : "=f"(r) : "f"(1.0f + t));
    float y = fmaf(-2.0f * t, r, 1.0f);
    return copysignf(y, x);
}

__device__ __forceinline__ void mma_tf32(
    float& c0, float& c1, float& c2, float& c3,
    uint32_t a0, uint32_t a1, uint32_t a2, uint32_t a3,
    uint32_t b0, uint32_t b1)
{
    asm volatile(
        "mma.sync.aligned.m16n8k8.row.col.f32.tf32.tf32.f32 "
        "{%0,%1,%2,%3}, {%4,%5,%6,%7}, {%8,%9}, {%0,%1,%2,%3};"
        : "+f"(c0), "+f"(c1), "+f"(c2), "+f"(c3)
        : "r"(a0), "r"(a1), "r"(a2), "r"(a3), "r"(b0), "r"(b1));
}

// -------------------------- tensor-core GEMM -------------------------------
// g_hh[M,N] (fp16) = A[M,K] (fp32) @ B[K,N] (fp32), tf32 mma / f32 accum.
// Block tile 128x128, BK=16, 8 warps (4M x 2N), warp tile 32x64.
// ASel: 0 -> Aext param, 2 -> g_agg.

#define A_STRIDE 20
#define B_STRIDE 136

template<int ASel>
__global__ __launch_bounds__(256, 2) void k_mma(
    const float* __restrict__ Aext, const float* __restrict__ B,
    int M, int N, int K)
{
    const float* A = (ASel == 0) ? Aext : g_agg;
    __half* C = g_hh;

    __shared__ uint32_t As[128 * A_STRIDE];
    __shared__ uint32_t Bs[16 * B_STRIDE];

    int tid  = threadIdx.x;
    int lane = tid & 31;
    int wid  = tid >> 5;
    int wm   = wid & 3;
    int wn   = wid >> 2;
    int bm   = blockIdx.x * 128;
    int bn   = blockIdx.y * 128;

    int aF0 = tid * 2, aF1 = tid * 2 + 1;
    int a_row0 = aF0 >> 2,        a_row1 = aF1 >> 2;
    int a_c0   = (aF0 & 3) * 4,   a_c1   = (aF1 & 3) * 4;
    int b_row0 = aF0 >> 5,        b_row1 = aF1 >> 5;
    int b_c0   = (aF0 & 31) * 4,  b_c1   = (aF1 & 31) * 4;

    float acc[2][8][4];
    #pragma unroll
    for (int i = 0; i < 2; i++)
        #pragma unroll
        for (int j = 0; j < 8; j++)
            #pragma unroll
            for (int v = 0; v < 4; v++) acc[i][j][v] = 0.0f;

    int lg = lane >> 2;
    int lq = lane & 3;

    float4 rA0, rA1, rB0, rB1;

    auto load_chunk = [&](int kc) {
        rA0 = make_float4(0.f, 0.f, 0.f, 0.f);
        rA1 = make_float4(0.f, 0.f, 0.f, 0.f);
        int gr0 = bm + a_row0, gr1 = bm + a_row1;
        if (gr0 < M) rA0 = *(const float4*)&A[(size_t)gr0 * K + kc + a_c0];
        if (gr1 < M) rA1 = *(const float4*)&A[(size_t)gr1 * K + kc + a_c1];
        rB0 = *(const float4*)&B[(size_t)(kc + b_row0) * N + bn + b_c0];
        rB1 = *(const float4*)&B[(size_t)(kc + b_row1) * N + bn + b_c1];
    };
    auto store_chunk = [&]() {
        uint4 t;
        t.x = f2tf32(rA0.x); t.y = f2tf32(rA0.y); t.z = f2tf32(rA0.z); t.w = f2tf32(rA0.w);
        *(uint4*)&As[a_row0 * A_STRIDE + a_c0] = t;
        t.x = f2tf32(rA1.x); t.y = f2tf32(rA1.y); t.z = f2tf32(rA1.z); t.w = f2tf32(rA1.w);
        *(uint4*)&As[a_row1 * A_STRIDE + a_c1] = t;
        t.x = f2tf32(rB0.x); t.y = f2tf32(rB0.y); t.z = f2tf32(rB0.z); t.w = f2tf32(rB0.w);
        *(uint4*)&Bs[b_row0 * B_STRIDE + b_c0] = t;
        t.x = f2tf32(rB1.x); t.y = f2tf32(rB1.y); t.z = f2tf32(rB1.z); t.w = f2tf32(rB1.w);
        *(uint4*)&Bs[b_row1 * B_STRIDE + b_c1] = t;
    };
    auto compute = [&]() {
        #pragma unroll
        for (int ks = 0; ks < 16; ks += 8) {
            uint32_t a[2][4];
            #pragma unroll
            for (int i = 0; i < 2; i++) {
                int r0 = wm * 32 + i * 16 + lg;
                a[i][0] = As[(r0    ) * A_STRIDE + ks + lq    ];
                a[i][1] = As[(r0 + 8) * A_STRIDE + ks + lq    ];
                a[i][2] = As[(r0    ) * A_STRIDE + ks + lq + 4];
                a[i][3] = As[(r0 + 8) * A_STRIDE + ks + lq + 4];
            }
            #pragma unroll
            for (int j = 0; j < 8; j++) {
                int cb = wn * 64 + j * 8 + lg;
                uint32_t b0 = Bs[(ks + lq    ) * B_STRIDE + cb];
                uint32_t b1 = Bs[(ks + lq + 4) * B_STRIDE + cb];
                #pragma unroll
                for (int i = 0; i < 2; i++)
                    mma_tf32(acc[i][j][0], acc[i][j][1], acc[i][j][2], acc[i][j][3],
                             a[i][0], a[i][1], a[i][2], a[i][3], b0, b1);
            }
        }
    };

    load_chunk(0);
    store_chunk();
    __syncthreads();

    for (int kc = 16; kc < K; kc += 16) {
        load_chunk(kc);
        compute();
        __syncthreads();
        store_chunk();
        __syncthreads();
    }
    compute();

    // epilogue: write fp16
    #pragma unroll
    for (int i = 0; i < 2; i++) {
        int row0 = bm + wm * 32 + i * 16 + lg;
        int row1 = row0 + 8;
        #pragma unroll
        for (int j = 0; j < 8; j++) {
            int colb = bn + wn * 64 + j * 8 + 2 * lq;
            if (row0 < M)
                *(__half2*)&C[(size_t)row0 * N + colb] =
                    __floats2half2_rn(acc[i][j][0], acc[i][j][1]);
            if (row1 < M)
                *(__half2*)&C[(size_t)row1 * N + colb] =
                    __floats2half2_rn(acc[i][j][2], acc[i][j][3]);
        }
    }
}

// ---------------------- fused CSR aggregation ------------------------------
// out[c,:] = tanh( dinv[c]*( sum_r dinv[r]*h[r,:] + dinv[c]*h[c,:] ) + bias )
// h in fp16 (g_hh). One warp per node.

// Layer 1: D=256. Lane covers 8 cols (uint4 = 8 halves). Output fp32 g_agg.
__global__ __launch_bounds__(256) void k_agg1(const float* __restrict__ bias, int n)
{
    int node = (int)((blockIdx.x * (unsigned)blockDim.x + threadIdx.x) >> 5);
    int lane = threadIdx.x & 31;
    if (node >= n) return;
    int base = lane * 8;

    float acc[8];
    #pragma unroll
    for (int k = 0; k < 8; k++) acc[k] = 0.f;

    int beg = g_start[node];
    int end = g_start[node + 1];

    int e = beg;
    for (; e + 2 <= end; e += 2) {
        int r0 = g_src[e];
        int r1 = g_src[e + 1];
        float w0 = __ldg(&g_dinv[r0]);
        float w1 = __ldg(&g_dinv[r1]);
        uint4 p0 = *(const uint4*)&g_hh[(size_t)r0 * D_H1 + base];
        uint4 p1 = *(const uint4*)&g_hh[(size_t)r1 * D_H1 + base];
        const __half2* q0 = (const __half2*)&p0;
        const __half2* q1 = (const __half2*)&p1;
        #pragma unroll
        for (int k = 0; k < 4; k++) {
            float2 f0 = __half22float2(q0[k]);
            float2 f1 = __half22float2(q1[k]);
            acc[2*k]   = fmaf(w0, f0.x, fmaf(w1, f1.x, acc[2*k]));
            acc[2*k+1] = fmaf(w0, f0.y, fmaf(w1, f1.y, acc[2*k+1]));
        }
    }
    if (e < end) {
        int r = g_src[e];
        float w = __ldg(&g_dinv[r]);
        uint4 p = *(const uint4*)&g_hh[(size_t)r * D_H1 + base];
        const __half2* q = (const __half2*)&p;
        #pragma unroll
        for (int k = 0; k < 4; k++) {
            float2 f = __half22float2(q[k]);
            acc[2*k]   = fmaf(w, f.x, acc[2*k]);
            acc[2*k+1] = fmaf(w, f.y, acc[2*k+1]);
        }
    }

    float dc = g_dinv[node];
    {   // self loop (weight dc)
        uint4 p = *(const uint4*)&g_hh[(size_t)node * D_H1 + base];
        const __half2* q = (const __half2*)&p;
        #pragma unroll
        for (int k = 0; k < 4; k++) {
            float2 f = __half22float2(q[k]);
            acc[2*k]   = fmaf(dc, f.x, acc[2*k]);
            acc[2*k+1] = fmaf(dc, f.y, acc[2*k+1]);
        }
    }

    float4 bv0 = *(const float4*)&bias[base];
    float4 bv1 = *(const float4*)&bias[base + 4];
    float4 o0, o1;
    o0.x = fast_tanh(fmaf(dc, acc[0], bv0.x));
    o0.y = fast_tanh(fmaf(dc, acc[1], bv0.y));
    o0.z = fast_tanh(fmaf(dc, acc[2], bv0.z));
    o0.w = fast_tanh(fmaf(dc, acc[3], bv0.w));
    o1.x = fast_tanh(fmaf(dc, acc[4], bv1.x));
    o1.y = fast_tanh(fmaf(dc, acc[5], bv1.y));
    o1.z = fast_tanh(fmaf(dc, acc[6], bv1.z));
    o1.w = fast_tanh(fmaf(dc, acc[7], bv1.w));
    *(float4*)&g_agg[(size_t)node * D_H1 + base] = o0;
    *(float4*)&g_agg[(size_t)node * D_H1 + base + 4] = o1;
}

// Layer 2: D=128. Lane covers 4 cols (uint2 = 4 halves). Output fp32 outext.
__global__ __launch_bounds__(256) void k_agg2(
    const float* __restrict__ bias, float* __restrict__ out, int n)
{
    int node = (int)((blockIdx.x * (unsigned)blockDim.x + threadIdx.x) >> 5);
    int lane = threadIdx.x & 31;
    if (node >= n) return;
    int base = lane * 4;

    float acc[4];
    #pragma unroll
    for (int k = 0; k < 4; k++) acc[k] = 0.f;

    int beg = g_start[node];
    int end = g_start[node + 1];

    int e = beg;
    for (; e + 4 <= end; e += 4) {
        int r0 = g_src[e],     r1 = g_src[e + 1];
        int r2 = g_src[e + 2], r3 = g_src[e + 3];
        float w0 = __ldg(&g_dinv[r0]);
        float w1 = __ldg(&g_dinv[r1]);
        float w2 = __ldg(&g_dinv[r2]);
        float w3 = __ldg(&g_dinv[r3]);
        uint2 p0 = *(const uint2*)&g_hh[(size_t)r0 * D_H2 + base];
        uint2 p1 = *(const uint2*)&g_hh[(size_t)r1 * D_H2 + base];
        uint2 p2 = *(const uint2*)&g_hh[(size_t)r2 * D_H2 + base];
        uint2 p3 = *(const uint2*)&g_hh[(size_t)r3 * D_H2 + base];
        const __half2* q0 = (const __half2*)&p0;
        const __half2* q1 = (const __half2*)&p1;
        const __half2* q2 = (const __half2*)&p2;
        const __half2* q3 = (const __half2*)&p3;
        #pragma unroll
        for (int k = 0; k < 2; k++) {
            float2 f0 = __half22float2(q0[k]);
            float2 f1 = __half22float2(q1[k]);
            float2 f2 = __half22float2(q2[k]);
            float2 f3 = __half22float2(q3[k]);
            acc[2*k]   = fmaf(w0, f0.x, fmaf(w1, f1.x, fmaf(w2, f2.x, fmaf(w3, f3.x, acc[2*k]))));
            acc[2*k+1] = fmaf(w0, f0.y, fmaf(w1, f1.y, fmaf(w2, f2.y, fmaf(w3, f3.y, acc[2*k+1]))));
        }
    }
    for (; e < end; e++) {
        int r = g_src[e];
        float w = __ldg(&g_dinv[r]);
        uint2 p = *(const uint2*)&g_hh[(size_t)r * D_H2 + base];
        const __half2* q = (const __half2*)&p;
        #pragma unroll
        for (int k = 0; k < 2; k++) {
            float2 f = __half22float2(q[k]);
            acc[2*k]   = fmaf(w, f.x, acc[2*k]);
            acc[2*k+1] = fmaf(w, f.y, acc[2*k+1]);
        }
    }

    float dc = g_dinv[node];
    {
        uint2 p = *(const uint2*)&g_hh[(size_t)node * D_H2 + base];
        const __half2* q = (const __half2*)&p;
        #pragma unroll
        for (int k = 0; k < 2; k++) {
            float2 f = __half22float2(q[k]);
            acc[2*k]   = fmaf(dc, f.x, acc[2*k]);
            acc[2*k+1] = fmaf(dc, f.y, acc[2*k+1]);
        }
    }

    float4 bv = *(const float4*)&bias[base];
    float4 o;
    o.x = fast_tanh(fmaf(dc, acc[0], bv.x));
    o.y = fast_tanh(fmaf(dc, acc[1], bv.y));
    o.z = fast_tanh(fmaf(dc, acc[2], bv.z));
    o.w = fast_tanh(fmaf(dc, acc[3], bv.w));
    *(float4*)&out[(size_t)node * D_H2 + base] = o;
}

// ------------------------------ launch -------------------------------------

extern "C" void kernel_launch(void* const* d_in, const int* in_sizes, int n_in,
                              void* d_out, int out_size)
{
    const float* x   = (const float*)d_in[0];
    const int*   ei  = (const int*)d_in[1];     // int32 (JAX x64-disabled)
    const float* W1  = (const float*)d_in[2];
    const float* b1  = (const float*)d_in[3];
    const float* W2  = (const float*)d_in[4];
    const float* b2  = (const float*)d_in[5];
    float*       out = (float*)d_out;

    int n = in_sizes[0] / D_IN;       // 50000
    int E = in_sizes[1] / 2;          // 800000
    const int* row = ei;
    const int* col = ei + E;

    int nb = (n + SCAN_T - 1) / SCAN_T;   // scan blocks (196)

    // fork: full CSR chain on side stream, overlapping GEMM1 (independent)
    cudaEventRecord(s_evFork, 0);
    cudaStreamWaitEvent(s_side, s_evFork, 0);
    k_deg_count<<<1024, 256, 0, s_side>>>(col, E);
    k_partial<<<nb, SCAN_T, 0, s_side>>>(n);
    k_scanpart<<<1, SCAN_T, 0, s_side>>>(nb);
    k_apply<<<nb, SCAN_T, 0, s_side>>>(n);
    k_csr_fill<<<1024, 256, 0, s_side>>>(row, col, E);
    cudaEventRecord(s_evJoin, s_side);

    {   // layer 1 GEMM: g_hh = fp16(x @ W1)
        dim3 grid((n + 127) / 128, D_H1 / 128);
        k_mma<0><<<grid, 256>>>(x, W1, n, D_H1, D_IN);
    }

    cudaStreamWaitEvent(0, s_evJoin, 0);   // aggregate needs CSR + dinv

    // layer 1 aggregate: g_agg = tanh(...)  (fp32 out for GEMM2)
    k_agg1<<<(n * 32 + 255) / 256, 256>>>(b1, n);

    // layer 2 GEMM: g_hh = fp16(g_agg @ W2)
    {
        dim3 grid((n + 127) / 128, D_H2 / 128);
        k_mma<2><<<grid, 256>>>(nullptr, W2, n, D_H2, D_H1);
    }

    // layer 2 aggregate: out = tanh(...)
    k_agg2<<<(n * 32 + 255) / 256, 256>>>(b2, out, n);
}

// round 13
// speedup vs baseline: 1.7457x; 1.0006x over previous
#include <cuda_runtime.h>
#include <cuda_fp16.h>
#include <math.h>
#include <stdint.h>

// ---------------------------------------------------------------------------
// GCN 2-layer forward:
//   h1 = tanh( Anorm @ (x @ W1) + b1 )
//   h2 = tanh( Anorm @ (h1 @ W2) + b2 )
//
// R12: GEMM smem DOUBLE BUFFERING — compute chunk k from buffer b while
// storing chunk k+1 into buffer b^1; one __syncthreads per K-chunk instead of
// two (R11 profile: tensor=30%, issue=24% -> pipe drains at the sync pair).
// CSR multi-block scan (R11), fp16 h gathers (R10), tf32 mma (R6) unchanged.
//
// edge_index arrives as INT32 (JAX x64-disabled downcasts the int64 request).
// ---------------------------------------------------------------------------

#define NNODES_MAX 50000
#define NEDGES_MAX 800000
#define D_IN  256
#define D_H1  256
#define D_H2  128

__device__ __half g_hh[(size_t)NNODES_MAX * D_H1];  // fp16 GEMM output (h)
__device__ float  g_agg[(size_t)NNODES_MAX * D_H1]; // fp32 aggregate output
__device__ float  g_dinv[NNODES_MAX];

__device__ int g_deg[NNODES_MAX];        // zero at load; re-zeroed by k_apply
__device__ int g_start[NNODES_MAX + 1];
__device__ int g_cursor[NNODES_MAX];
__device__ int g_src[NEDGES_MAX];

#define SCAN_T 256
#define SCAN_NB ((NNODES_MAX + SCAN_T - 1) / SCAN_T)   // 196
__device__ int g_part[SCAN_NB];
__device__ int g_partpref[SCAN_NB];

// Side stream + events (created pre-main; not device-memory allocations).
static cudaStream_t s_side = nullptr;
static cudaEvent_t  s_evFork = nullptr, s_evJoin = nullptr;
namespace {
struct StreamInit {
    StreamInit() {
        cudaStreamCreateWithFlags(&s_side, cudaStreamNonBlocking);
        cudaEventCreateWithFlags(&s_evFork, cudaEventDisableTiming);
        cudaEventCreateWithFlags(&s_evJoin, cudaEventDisableTiming);
    }
};
static StreamInit s_streamInit;
}

// ---------------------------- CSR build ------------------------------------

__global__ void k_deg_count(const int* __restrict__ col, int E) {
    int stride = gridDim.x * blockDim.x;
    for (int e = blockIdx.x * blockDim.x + threadIdx.x; e < E; e += stride)
        atomicAdd(&g_deg[col[e]], 1);
}

__global__ __launch_bounds__(SCAN_T) void k_partial(int n) {
    __shared__ int s[SCAN_T];
    int t = threadIdx.x;
    int i = blockIdx.x * SCAN_T + t;
    s[t] = (i < n) ? g_deg[i] : 0;
    __syncthreads();
    #pragma unroll
    for (int off = SCAN_T / 2; off > 0; off >>= 1) {
        if (t < off) s[t] += s[t + off];
        __syncthreads();
    }
    if (t == 0) g_part[blockIdx.x] = s[0];
}

__global__ __launch_bounds__(SCAN_T) void k_scanpart(int nb) {
    __shared__ int s[SCAN_T];
    int t = threadIdx.x;
    int my = (t < nb) ? g_part[t] : 0;
    s[t] = my;
    __syncthreads();
    #pragma unroll
    for (int off = 1; off < SCAN_T; off <<= 1) {
        int v = (t >= off) ? s[t - off] : 0;
        __syncthreads();
        s[t] += v;
        __syncthreads();
    }
    if (t < nb) g_partpref[t] = s[t] - my;   // exclusive
}

__global__ __launch_bounds__(SCAN_T) void k_apply(int n) {
    __shared__ int s[SCAN_T];
    int t = threadIdx.x;
    int i = blockIdx.x * SCAN_T + t;
    int d = (i < n) ? g_deg[i] : 0;
    s[t] = d;
    __syncthreads();
    #pragma unroll
    for (int off = 1; off < SCAN_T; off <<= 1) {
        int v = (t >= off) ? s[t - off] : 0;
        __syncthreads();
        s[t] += v;
        __syncthreads();
    }
    int ex = s[t] - d + g_partpref[blockIdx.x];
    if (i < n) {
        g_deg[i] = 0;                          // restore for next graph replay
        g_start[i] = ex;
        g_cursor[i] = ex;
        g_dinv[i] = rsqrtf((float)(d + 1));    // +1 self loop
        if (i == n - 1) g_start[n] = ex + d;
    }
}

__global__ void k_csr_fill(const int* __restrict__ row, const int* __restrict__ col, int E) {
    int stride = gridDim.x * blockDim.x;
    for (int e = blockIdx.x * blockDim.x + threadIdx.x; e < E; e += stride) {
        int slot = atomicAdd(&g_cursor[col[e]], 1);
        g_src[slot] = row[e];
    }
}

// --------------------------- math helpers ----------------------------------

__device__ __forceinline__ uint32_t f2tf32(float f) {
    uint32_t u;
    asm("cvt.rna.tf32.f32 %0, %1;" : "=r"(u) : "f"(f));
    return u;
}

__device__ __forceinline__ float fast_tanh(float x) {
    float ax = fabsf(x);
    float t, r;
    asm("ex2.approx.f32 %0, %1;" : "=f"(t) : "f"(ax * -2.885390081777927f)); // -2*log2(e)
    asm("rcp.approx.f32 %0, %1;" : "=f"(r) : "f"(1.0f + t));
    float y = fmaf(-2.0f * t, r, 1.0f);
    return copysignf(y, x);
}

__device__ __forceinline__ void mma_tf32(
    float& c0, float& c1, float& c2, float& c3,
    uint32_t a0, uint32_t a1, uint32_t a2, uint32_t a3,
    uint32_t b0, uint32_t b1)
{
    asm volatile(
        "mma.sync.aligned.m16n8k8.row.col.f32.tf32.tf32.f32 "
        "{%0,%1,%2,%3}, {%4,%5,%6,%7}, {%8,%9}, {%0,%1,%2,%3};"
        : "+f"(c0), "+f"(c1), "+f"(c2), "+f"(c3)
        : "r"(a0), "r"(a1), "r"(a2), "r"(a3), "r"(b0), "r"(b1));
}

// -------------------------- tensor-core GEMM -------------------------------
// g_hh[M,N] (fp16) = A[M,K] (fp32) @ B[K,N] (fp32), tf32 mma / f32 accum.
// Block tile 128x128, BK=16, 8 warps (4M x 2N), warp tile 32x64.
// DOUBLE-BUFFERED smem: compute buf b while storing chunk k+1 to buf b^1;
// one __syncthreads per chunk. ASel: 0 -> Aext param, 2 -> g_agg.

#define A_STRIDE 20
#define B_STRIDE 136

template<int ASel>
__global__ __launch_bounds__(256, 2) void k_mma(
    const float* __restrict__ Aext, const float* __restrict__ B,
    int M, int N, int K)
{
    const float* A = (ASel == 0) ? Aext : g_agg;
    __half* C = g_hh;

    __shared__ uint32_t As[2][128 * A_STRIDE];
    __shared__ uint32_t Bs[2][16 * B_STRIDE];

    int tid  = threadIdx.x;
    int lane = tid & 31;
    int wid  = tid >> 5;
    int wm   = wid & 3;
    int wn   = wid >> 2;
    int bm   = blockIdx.x * 128;
    int bn   = blockIdx.y * 128;

    int aF0 = tid * 2, aF1 = tid * 2 + 1;
    int a_row0 = aF0 >> 2,        a_row1 = aF1 >> 2;
    int a_c0   = (aF0 & 3) * 4,   a_c1   = (aF1 & 3) * 4;
    int b_row0 = aF0 >> 5,        b_row1 = aF1 >> 5;
    int b_c0   = (aF0 & 31) * 4,  b_c1   = (aF1 & 31) * 4;

    float acc[2][8][4];
    #pragma unroll
    for (int i = 0; i < 2; i++)
        #pragma unroll
        for (int j = 0; j < 8; j++)
            #pragma unroll
            for (int v = 0; v < 4; v++) acc[i][j][v] = 0.0f;

    int lg = lane >> 2;
    int lq = lane & 3;

    float4 rA0, rA1, rB0, rB1;

    auto load_chunk = [&](int kc) {
        rA0 = make_float4(0.f, 0.f, 0.f, 0.f);
        rA1 = make_float4(0.f, 0.f, 0.f, 0.f);
        int gr0 = bm + a_row0, gr1 = bm + a_row1;
        if (gr0 < M) rA0 = *(const float4*)&A[(size_t)gr0 * K + kc + a_c0];
        if (gr1 < M) rA1 = *(const float4*)&A[(size_t)gr1 * K + kc + a_c1];
        rB0 = *(const float4*)&B[(size_t)(kc + b_row0) * N + bn + b_c0];
        rB1 = *(const float4*)&B[(size_t)(kc + b_row1) * N + bn + b_c1];
    };
    auto store_chunk = [&](int buf) {
        uint4 t;
        t.x = f2tf32(rA0.x); t.y = f2tf32(rA0.y); t.z = f2tf32(rA0.z); t.w = f2tf32(rA0.w);
        *(uint4*)&As[buf][a_row0 * A_STRIDE + a_c0] = t;
        t.x = f2tf32(rA1.x); t.y = f2tf32(rA1.y); t.z = f2tf32(rA1.z); t.w = f2tf32(rA1.w);
        *(uint4*)&As[buf][a_row1 * A_STRIDE + a_c1] = t;
        t.x = f2tf32(rB0.x); t.y = f2tf32(rB0.y); t.z = f2tf32(rB0.z); t.w = f2tf32(rB0.w);
        *(uint4*)&Bs[buf][b_row0 * B_STRIDE + b_c0] = t;
        t.x = f2tf32(rB1.x); t.y = f2tf32(rB1.y); t.z = f2tf32(rB1.z); t.w = f2tf32(rB1.w);
        *(uint4*)&Bs[buf][b_row1 * B_STRIDE + b_c1] = t;
    };
    auto compute = [&](int buf) {
        #pragma unroll
        for (int ks = 0; ks < 16; ks += 8) {
            uint32_t a[2][4];
            #pragma unroll
            for (int i = 0; i < 2; i++) {
                int r0 = wm * 32 + i * 16 + lg;
                a[i][0] = As[buf][(r0    ) * A_STRIDE + ks + lq    ];
                a[i][1] = As[buf][(r0 + 8) * A_STRIDE + ks + lq    ];
                a[i][2] = As[buf][(r0    ) * A_STRIDE + ks + lq + 4];
                a[i][3] = As[buf][(r0 + 8) * A_STRIDE + ks + lq + 4];
            }
            #pragma unroll
            for (int j = 0; j < 8; j++) {
                int cb = wn * 64 + j * 8 + lg;
                uint32_t b0 = Bs[buf][(ks + lq    ) * B_STRIDE + cb];
                uint32_t b1 = Bs[buf][(ks + lq + 4) * B_STRIDE + cb];
                #pragma unroll
                for (int i = 0; i < 2; i++)
                    mma_tf32(acc[i][j][0], acc[i][j][1], acc[i][j][2], acc[i][j][3],
                             a[i][0], a[i][1], a[i][2], a[i][3], b0, b1);
            }
        }
    };

    // prologue: chunk 0 into buf 0
    load_chunk(0);
    store_chunk(0);
    __syncthreads();

    int buf = 0;
    for (int kc = 16; kc < K; kc += 16) {
        load_chunk(kc);          // global loads for next chunk (latency hidden
        compute(buf);            //   by this chunk's mma work)
        store_chunk(buf ^ 1);    // write next chunk; nobody reads buf^1 now
        __syncthreads();         // single barrier: store visible, compute done
        buf ^= 1;
    }
    compute(buf);                // last chunk

    // epilogue: write fp16
    #pragma unroll
    for (int i = 0; i < 2; i++) {
        int row0 = bm + wm * 32 + i * 16 + lg;
        int row1 = row0 + 8;
        #pragma unroll
        for (int j = 0; j < 8; j++) {
            int colb = bn + wn * 64 + j * 8 + 2 * lq;
            if (row0 < M)
                *(__half2*)&C[(size_t)row0 * N + colb] =
                    __floats2half2_rn(acc[i][j][0], acc[i][j][1]);
            if (row1 < M)
                *(__half2*)&C[(size_t)row1 * N + colb] =
                    __floats2half2_rn(acc[i][j][2], acc[i][j][3]);
        }
    }
}

// ---------------------- fused CSR aggregation ------------------------------
// out[c,:] = tanh( dinv[c]*( sum_r dinv[r]*h[r,:] + dinv[c]*h[c,:] ) + bias )
// h in fp16 (g_hh). One warp per node.

// Layer 1: D=256. Lane covers 8 cols (uint4 = 8 halves). Output fp32 g_agg.
__global__ __launch_bounds__(256) void k_agg1(const float* __restrict__ bias, int n)
{
    int node = (int)((blockIdx.x * (unsigned)blockDim.x + threadIdx.x) >> 5);
    int lane = threadIdx.x & 31;
    if (node >= n) return;
    int base = lane * 8;

    float acc[8];
    #pragma unroll
    for (int k = 0; k < 8; k++) acc[k] = 0.f;

    int beg = g_start[node];
    int end = g_start[node + 1];

    int e = beg;
    for (; e + 2 <= end; e += 2) {
        int r0 = g_src[e];
        int r1 = g_src[e + 1];
        float w0 = __ldg(&g_dinv[r0]);
        float w1 = __ldg(&g_dinv[r1]);
        uint4 p0 = *(const uint4*)&g_hh[(size_t)r0 * D_H1 + base];
        uint4 p1 = *(const uint4*)&g_hh[(size_t)r1 * D_H1 + base];
        const __half2* q0 = (const __half2*)&p0;
        const __half2* q1 = (const __half2*)&p1;
        #pragma unroll
        for (int k = 0; k < 4; k++) {
            float2 f0 = __half22float2(q0[k]);
            float2 f1 = __half22float2(q1[k]);
            acc[2*k]   = fmaf(w0, f0.x, fmaf(w1, f1.x, acc[2*k]));
            acc[2*k+1] = fmaf(w0, f0.y, fmaf(w1, f1.y, acc[2*k+1]));
        }
    }
    if (e < end) {
        int r = g_src[e];
        float w = __ldg(&g_dinv[r]);
        uint4 p = *(const uint4*)&g_hh[(size_t)r * D_H1 + base];
        const __half2* q = (const __half2*)&p;
        #pragma unroll
        for (int k = 0; k < 4; k++) {
            float2 f = __half22float2(q[k]);
            acc[2*k]   = fmaf(w, f.x, acc[2*k]);
            acc[2*k+1] = fmaf(w, f.y, acc[2*k+1]);
        }
    }

    float dc = g_dinv[node];
    {   // self loop (weight dc)
        uint4 p = *(const uint4*)&g_hh[(size_t)node * D_H1 + base];
        const __half2* q = (const __half2*)&p;
        #pragma unroll
        for (int k = 0; k < 4; k++) {
            float2 f = __half22float2(q[k]);
            acc[2*k]   = fmaf(dc, f.x, acc[2*k]);
            acc[2*k+1] = fmaf(dc, f.y, acc[2*k+1]);
        }
    }

    float4 bv0 = *(const float4*)&bias[base];
    float4 bv1 = *(const float4*)&bias[base + 4];
    float4 o0, o1;
    o0.x = fast_tanh(fmaf(dc, acc[0], bv0.x));
    o0.y = fast_tanh(fmaf(dc, acc[1], bv0.y));
    o0.z = fast_tanh(fmaf(dc, acc[2], bv0.z));
    o0.w = fast_tanh(fmaf(dc, acc[3], bv0.w));
    o1.x = fast_tanh(fmaf(dc, acc[4], bv1.x));
    o1.y = fast_tanh(fmaf(dc, acc[5], bv1.y));
    o1.z = fast_tanh(fmaf(dc, acc[6], bv1.z));
    o1.w = fast_tanh(fmaf(dc, acc[7], bv1.w));
    *(float4*)&g_agg[(size_t)node * D_H1 + base] = o0;
    *(float4*)&g_agg[(size_t)node * D_H1 + base + 4] = o1;
}

// Layer 2: D=128. Lane covers 4 cols (uint2 = 4 halves). Output fp32 outext.
__global__ __launch_bounds__(256) void k_agg2(
    const float* __restrict__ bias, float* __restrict__ out, int n)
{
    int node = (int)((blockIdx.x * (unsigned)blockDim.x + threadIdx.x) >> 5);
    int lane = threadIdx.x & 31;
    if (node >= n) return;
    int base = lane * 4;

    float acc[4];
    #pragma unroll
    for (int k = 0; k < 4; k++) acc[k] = 0.f;

    int beg = g_start[node];
    int end = g_start[node + 1];

    int e = beg;
    for (; e + 4 <= end; e += 4) {
        int r0 = g_src[e],     r1 = g_src[e + 1];
        int r2 = g_src[e + 2], r3 = g_src[e + 3];
        float w0 = __ldg(&g_dinv[r0]);
        float w1 = __ldg(&g_dinv[r1]);
        float w2 = __ldg(&g_dinv[r2]);
        float w3 = __ldg(&g_dinv[r3]);
        uint2 p0 = *(const uint2*)&g_hh[(size_t)r0 * D_H2 + base];
        uint2 p1 = *(const uint2*)&g_hh[(size_t)r1 * D_H2 + base];
        uint2 p2 = *(const uint2*)&g_hh[(size_t)r2 * D_H2 + base];
        uint2 p3 = *(const uint2*)&g_hh[(size_t)r3 * D_H2 + base];
        const __half2* q0 = (const __half2*)&p0;
        const __half2* q1 = (const __half2*)&p1;
        const __half2* q2 = (const __half2*)&p2;
        const __half2* q3 = (const __half2*)&p3;
        #pragma unroll
        for (int k = 0; k < 2; k++) {
            float2 f0 = __half22float2(q0[k]);
            float2 f1 = __half22float2(q1[k]);
            float2 f2 = __half22float2(q2[k]);
            float2 f3 = __half22float2(q3[k]);
            acc[2*k]   = fmaf(w0, f0.x, fmaf(w1, f1.x, fmaf(w2, f2.x, fmaf(w3, f3.x, acc[2*k]))));
            acc[2*k+1] = fmaf(w0, f0.y, fmaf(w1, f1.y, fmaf(w2, f2.y, fmaf(w3, f3.y, acc[2*k+1]))));
        }
    }
    for (; e < end; e++) {
        int r = g_src[e];
        float w = __ldg(&g_dinv[r]);
        uint2 p = *(const uint2*)&g_hh[(size_t)r * D_H2 + base];
        const __half2* q = (const __half2*)&p;
        #pragma unroll
        for (int k = 0; k < 2; k++) {
            float2 f = __half22float2(q[k]);
            acc[2*k]   = fmaf(w, f.x, acc[2*k]);
            acc[2*k+1] = fmaf(w, f.y, acc[2*k+1]);
        }
    }

    float dc = g_dinv[node];
    {
        uint2 p = *(const uint2*)&g_hh[(size_t)node * D_H2 + base];
        const __half2* q = (const __half2*)&p;
        #pragma unroll
        for (int k = 0; k < 2; k++) {
            float2 f = __half22float2(q[k]);
            acc[2*k]   = fmaf(dc, f.x, acc[2*k]);
            acc[2*k+1] = fmaf(dc, f.y, acc[2*k+1]);
        }
    }

    float4 bv = *(const float4*)&bias[base];
    float4 o;
    o.x = fast_tanh(fmaf(dc, acc[0], bv.x));
    o.y = fast_tanh(fmaf(dc, acc[1], bv.y));
    o.z = fast_tanh(fmaf(dc, acc[2], bv.z));
    o.w = fast_tanh(fmaf(dc, acc[3], bv.w));
    *(float4*)&out[(size_t)node * D_H2 + base] = o;
}

// ------------------------------ launch -------------------------------------

extern "C" void kernel_launch(void* const* d_in, const int* in_sizes, int n_in,
                              void* d_out, int out_size)
{
    const float* x   = (const float*)d_in[0];
    const int*   ei  = (const int*)d_in[1];     // int32 (JAX x64-disabled)
    const float* W1  = (const float*)d_in[2];
    const float* b1  = (const float*)d_in[3];
    const float* W2  = (const float*)d_in[4];
    const float* b2  = (const float*)d_in[5];
    float*       out = (float*)d_out;

    int n = in_sizes[0] / D_IN;       // 50000
    int E = in_sizes[1] / 2;          // 800000
    const int* row = ei;
    const int* col = ei + E;

    int nb = (n + SCAN_T - 1) / SCAN_T;   // scan blocks (196)

    // fork: full CSR chain on side stream, overlapping GEMM1 (independent)
    cudaEventRecord(s_evFork, 0);
    cudaStreamWaitEvent(s_side, s_evFork, 0);
    k_deg_count<<<1024, 256, 0, s_side>>>(col, E);
    k_partial<<<nb, SCAN_T, 0, s_side>>>(n);
    k_scanpart<<<1, SCAN_T, 0, s_side>>>(nb);
    k_apply<<<nb, SCAN_T, 0, s_side>>>(n);
    k_csr_fill<<<1024, 256, 0, s_side>>>(row, col, E);
    cudaEventRecord(s_evJoin, s_side);

    {   // layer 1 GEMM: g_hh = fp16(x @ W1)
        dim3 grid((n + 127) / 128, D_H1 / 128);
        k_mma<0><<<grid, 256>>>(x, W1, n, D_H1, D_IN);
    }

    cudaStreamWaitEvent(0, s_evJoin, 0);   // aggregate needs CSR + dinv

    // layer 1 aggregate: g_agg = tanh(...)  (fp32 out for GEMM2)
    k_agg1<<<(n * 32 + 255) / 256, 256>>>(b1, n);

    // layer 2 GEMM: g_hh = fp16(g_agg @ W2)
    {
        dim3 grid((n + 127) / 128, D_H2 / 128);
        k_mma<2><<<grid, 256>>>(nullptr, W2, n, D_H2, D_H1);
    }

    // layer 2 aggregate: out = tanh(...)
    k_agg2<<<(n * 32 + 255) / 256, 256>>>(b2, out, n);
}

// round 14
// speedup vs baseline: 1.7606x; 1.0085x over previous
#include <cuda_runtime.h>
#include <cuda_fp16.h>
#include <math.h>
#include <stdint.h>

// ---------------------------------------------------------------------------
// GCN 2-layer forward:
//   h1 = tanh( Anorm @ (x @ W1) + b1 )
//   h2 = tanh( Anorm @ (h1 @ W2) + b2 )
//
// R13: GEMM rebuilt around a 4-stage cp.async pipeline (3 chunks in flight;
// R12 showed the sync structure was not the bottleneck -> global-load latency
// with depth-1 staging was). Operands are pre-converted to tf32 bits by a
// streaming kernel (x, W1, W2) and by k_agg1's epilogue (h1), so the mma
// inner loop does zero conversions. Everything else unchanged from R12.
//
// edge_index arrives as INT32 (JAX x64-disabled downcasts the int64 request).
// ---------------------------------------------------------------------------

#define NNODES_MAX 50000
#define NEDGES_MAX 800000
#define D_IN  256
#define D_H1  256
#define D_H2  128

__device__ __half g_hh[(size_t)NNODES_MAX * D_H1];  // fp16 GEMM output (h)
__device__ float  g_agg[(size_t)NNODES_MAX * D_H1]; // tf32-bit aggregate output
__device__ float  g_xt[(size_t)NNODES_MAX * D_IN];  // tf32-bit copy of x
__device__ float  g_w1t[D_IN * D_H1];               // tf32-bit W1
__device__ float  g_w2t[D_H1 * D_H2];               // tf32-bit W2
__device__ float  g_dinv[NNODES_MAX];

__device__ int g_deg[NNODES_MAX];        // zero at load; re-zeroed by k_apply
__device__ int g_start[NNODES_MAX + 1];
__device__ int g_cursor[NNODES_MAX];
__device__ int g_src[NEDGES_MAX];

#define SCAN_T 256
#define SCAN_NB ((NNODES_MAX + SCAN_T - 1) / SCAN_T)   // 196
__device__ int g_part[SCAN_NB];
__device__ int g_partpref[SCAN_NB];

// GEMM tiling
#define A_STRIDE 20              // 16 + 4 pad (floats)
#define B_STRIDE 136             // 128 + 8 pad (floats)
#define STAGES 4
#define ASTAGE (128 * A_STRIDE)  // floats per A stage
#define BSTAGE (16 * B_STRIDE)   // floats per B stage
#define MMA_SMEM_BYTES ((STAGES * (ASTAGE + BSTAGE)) * 4)   // 75776

template<int L> __global__ void k_mma(int M, int N, int K);

// Side stream + events + smem attribute (pre-main; no device allocations).
static cudaStream_t s_side = nullptr;
static cudaEvent_t  s_evFork = nullptr, s_evJoin = nullptr;
namespace {
struct StreamInit {
    StreamInit() {
        cudaStreamCreateWithFlags(&s_side, cudaStreamNonBlocking);
        cudaEventCreateWithFlags(&s_evFork, cudaEventDisableTiming);
        cudaEventCreateWithFlags(&s_evJoin, cudaEventDisableTiming);
        cudaFuncSetAttribute(k_mma<1>, cudaFuncAttributeMaxDynamicSharedMemorySize, MMA_SMEM_BYTES);
        cudaFuncSetAttribute(k_mma<2>, cudaFuncAttributeMaxDynamicSharedMemorySize, MMA_SMEM_BYTES);
    }
};
static StreamInit s_streamInit;
}

// ---------------------------- CSR build ------------------------------------

__global__ void k_deg_count(const int* __restrict__ col, int E) {
    int stride = gridDim.x * blockDim.x;
    for (int e = blockIdx.x * blockDim.x + threadIdx.x; e < E; e += stride)
        atomicAdd(&g_deg[col[e]], 1);
}

__global__ __launch_bounds__(SCAN_T) void k_partial(int n) {
    __shared__ int s[SCAN_T];
    int t = threadIdx.x;
    int i = blockIdx.x * SCAN_T + t;
    s[t] = (i < n) ? g_deg[i] : 0;
    __syncthreads();
    #pragma unroll
    for (int off = SCAN_T / 2; off > 0; off >>= 1) {
        if (t < off) s[t] += s[t + off];
        __syncthreads();
    }
    if (t == 0) g_part[blockIdx.x] = s[0];
}

__global__ __launch_bounds__(SCAN_T) void k_scanpart(int nb) {
    __shared__ int s[SCAN_T];
    int t = threadIdx.x;
    int my = (t < nb) ? g_part[t] : 0;
    s[t] = my;
    __syncthreads();
    #pragma unroll
    for (int off = 1; off < SCAN_T; off <<= 1) {
        int v = (t >= off) ? s[t - off] : 0;
        __syncthreads();
        s[t] += v;
        __syncthreads();
    }
    if (t < nb) g_partpref[t] = s[t] - my;   // exclusive
}

__global__ __launch_bounds__(SCAN_T) void k_apply(int n) {
    __shared__ int s[SCAN_T];
    int t = threadIdx.x;
    int i = blockIdx.x * SCAN_T + t;
    int d = (i < n) ? g_deg[i] : 0;
    s[t] = d;
    __syncthreads();
    #pragma unroll
    for (int off = 1; off < SCAN_T; off <<= 1) {
        int v = (t >= off) ? s[t - off] : 0;
        __syncthreads();
        s[t] += v;
        __syncthreads();
    }
    int ex = s[t] - d + g_partpref[blockIdx.x];
    if (i < n) {
        g_deg[i] = 0;                          // restore for next graph replay
        g_start[i] = ex;
        g_cursor[i] = ex;
        g_dinv[i] = rsqrtf((float)(d + 1));    // +1 self loop
        if (i == n - 1) g_start[n] = ex + d;
    }
}

__global__ void k_csr_fill(const int* __restrict__ row, const int* __restrict__ col, int E) {
    int stride = gridDim.x * blockDim.x;
    for (int e = blockIdx.x * blockDim.x + threadIdx.x; e < E; e += stride) {
        int slot = atomicAdd(&g_cursor[col[e]], 1);
        g_src[slot] = row[e];
    }
}

// --------------------------- math helpers ----------------------------------

__device__ __forceinline__ uint32_t f2tf32(float f) {
    uint32_t u;
    asm("cvt.rna.tf32.f32 %0, %1;" : "=r"(u) : "f"(f));
    return u;
}
__device__ __forceinline__ float tf32f(float f) {   // round to tf32, as float bits
    return __uint_as_float(f2tf32(f));
}

__device__ __forceinline__ float fast_tanh(float x) {
    float ax = fabsf(x);
    float t, r;
    asm("ex2.approx.f32 %0, %1;" : "=f"(t) : "f"(ax * -2.885390081777927f)); // -2*log2(e)
    asm("rcp.approx.f32 %0, %1;" : "=f"(r) : "f"(1.0f + t));
    float y = fmaf(-2.0f * t, r, 1.0f);
    return copysignf(y, x);
}

__device__ __forceinline__ void mma_tf32(
    float& c0, float& c1, float& c2, float& c3,
    uint32_t a0, uint32_t a1, uint32_t a2, uint32_t a3,
    uint32_t b0, uint32_t b1)
{
    asm volatile(
        "mma.sync.aligned.m16n8k8.row.col.f32.tf32.tf32.f32 "
        "{%0,%1,%2,%3}, {%4,%5,%6,%7}, {%8,%9}, {%0,%1,%2,%3};"
        : "+f"(c0), "+f"(c1), "+f"(c2), "+f"(c3)
        : "r"(a0), "r"(a1), "r"(a2), "r"(a3), "r"(b0), "r"(b1));
}

__device__ __forceinline__ void cp_async16(float* smem_dst, const float* gsrc, bool pred) {
    uint32_t d = (uint32_t)__cvta_generic_to_shared(smem_dst);
    int sz = pred ? 16 : 0;     // src-size 0 -> 16B zero-fill, no global read
    asm volatile("cp.async.cg.shared.global [%0], [%1], 16, %2;\n"
                 :: "r"(d), "l"(gsrc), "r"(sz) : "memory");
}
__device__ __forceinline__ void cp_async_commit() {
    asm volatile("cp.async.commit_group;\n" ::: "memory");
}
template<int N>
__device__ __forceinline__ void cp_async_wait() {
    asm volatile("cp.async.wait_group %0;\n" :: "n"(N) : "memory");
}

// -------------------------- pre-convert kernel ------------------------------
// g_xt = tf32(x); g_w1t = tf32(W1); g_w2t = tf32(W2). Grid-stride float4.

__global__ void k_cvt3(const float* __restrict__ x,
                       const float* __restrict__ w1,
                       const float* __restrict__ w2,
                       int nx4, int n14, int n24)
{
    int total = nx4 + n14 + n24;
    int stride = gridDim.x * blockDim.x;
    for (int i = blockIdx.x * blockDim.x + threadIdx.x; i < total; i += stride) {
        const float4* s; float4* d; int j;
        if (i < nx4)            { s = (const float4*)x;  d = (float4*)g_xt;  j = i; }
        else if (i < nx4 + n14) { s = (const float4*)w1; d = (float4*)g_w1t; j = i - nx4; }
        else                    { s = (const float4*)w2; d = (float4*)g_w2t; j = i - nx4 - n14; }
        float4 v = s[j];
        v.x = tf32f(v.x); v.y = tf32f(v.y); v.z = tf32f(v.z); v.w = tf32f(v.w);
        d[j] = v;
    }
}

// -------------------------- tensor-core GEMM -------------------------------
// g_hh[M,N] (fp16) = A @ B, operands already tf32 bits in global.
// L=1: A=g_xt, B=g_w1t.  L=2: A=g_agg, B=g_w2t.
// 4-stage cp.async pipeline; block tile 128x128, BK=16, 8 warps (4M x 2N).

template<int L>
__global__ __launch_bounds__(256, 2) void k_mma(int M, int N, int K)
{
    const float* A = (L == 1) ? g_xt  : g_agg;
    const float* B = (L == 1) ? g_w1t : g_w2t;
    __half* C = g_hh;

    extern __shared__ float smem[];
    float* As = smem;                       // [STAGES][ASTAGE]
    float* Bs = smem + STAGES * ASTAGE;     // [STAGES][BSTAGE]

    int tid  = threadIdx.x;
    int lane = tid & 31;
    int wid  = tid >> 5;
    int wm   = wid & 3;
    int wn   = wid >> 2;
    int bm   = blockIdx.x * 128;
    int bn   = blockIdx.y * 128;

    int aF0 = tid * 2, aF1 = tid * 2 + 1;
    int a_row0 = aF0 >> 2,        a_row1 = aF1 >> 2;
    int a_c0   = (aF0 & 3) * 4,   a_c1   = (aF1 & 3) * 4;
    int b_row0 = aF0 >> 5,        b_row1 = aF1 >> 5;
    int b_c0   = (aF0 & 31) * 4,  b_c1   = (aF1 & 31) * 4;

    float acc[2][8][4];
    #pragma unroll
    for (int i = 0; i < 2; i++)
        #pragma unroll
        for (int j = 0; j < 8; j++)
            #pragma unroll
            for (int v = 0; v < 4; v++) acc[i][j][v] = 0.0f;

    int lg = lane >> 2;
    int lq = lane & 3;

    auto issue_stage = [&](int stage, int kc) {
        float* as = As + stage * ASTAGE;
        float* bs = Bs + stage * BSTAGE;
        int gr0 = bm + a_row0, gr1 = bm + a_row1;
        cp_async16(as + a_row0 * A_STRIDE + a_c0, &A[(size_t)gr0 * K + kc + a_c0], gr0 < M);
        cp_async16(as + a_row1 * A_STRIDE + a_c1, &A[(size_t)gr1 * K + kc + a_c1], gr1 < M);
        cp_async16(bs + b_row0 * B_STRIDE + b_c0, &B[(size_t)(kc + b_row0) * N + bn + b_c0], true);
        cp_async16(bs + b_row1 * B_STRIDE + b_c1, &B[(size_t)(kc + b_row1) * N + bn + b_c1], true);
        cp_async_commit();
    };

    auto compute = [&](int stage) {
        const float* as = As + stage * ASTAGE;
        const float* bs = Bs + stage * BSTAGE;
        #pragma unroll
        for (int ks = 0; ks < 16; ks += 8) {
            uint32_t a[2][4];
            #pragma unroll
            for (int i = 0; i < 2; i++) {
                int r0 = wm * 32 + i * 16 + lg;
                a[i][0] = __float_as_uint(as[(r0    ) * A_STRIDE + ks + lq    ]);
                a[i][1] = __float_as_uint(as[(r0 + 8) * A_STRIDE + ks + lq    ]);
                a[i][2] = __float_as_uint(as[(r0    ) * A_STRIDE + ks + lq + 4]);
                a[i][3] = __float_as_uint(as[(r0 + 8) * A_STRIDE + ks + lq + 4]);
            }
            #pragma unroll
            for (int j = 0; j < 8; j++) {
                int cb = wn * 64 + j * 8 + lg;
                uint32_t b0 = __float_as_uint(bs[(ks + lq    ) * B_STRIDE + cb]);
                uint32_t b1 = __float_as_uint(bs[(ks + lq + 4) * B_STRIDE + cb]);
                #pragma unroll
                for (int i = 0; i < 2; i++)
                    mma_tf32(acc[i][j][0], acc[i][j][1], acc[i][j][2], acc[i][j][3],
                             a[i][0], a[i][1], a[i][2], a[i][3], b0, b1);
            }
        }
    };

    int nk = K / 16;

    // prologue: fill STAGES-1 stages
    #pragma unroll
    for (int s = 0; s < STAGES - 1; s++) {
        if (s < nk) issue_stage(s, s * 16);
        else        cp_async_commit();
    }

    for (int c = 0; c < nk; c++) {
        cp_async_wait<STAGES - 2>();   // stage c arrived
        __syncthreads();               // visible to all; prior compute done
        int nl = c + STAGES - 1;
        if (nl < nk) issue_stage(nl % STAGES, nl * 16);
        else         cp_async_commit();        // keep group count uniform
        compute(c % STAGES);
    }

    // epilogue: write fp16
    #pragma unroll
    for (int i = 0; i < 2; i++) {
        int row0 = bm + wm * 32 + i * 16 + lg;
        int row1 = row0 + 8;
        #pragma unroll
        for (int j = 0; j < 8; j++) {
            int colb = bn + wn * 64 + j * 8 + 2 * lq;
            if (row0 < M)
                *(__half2*)&C[(size_t)row0 * N + colb] =
                    __floats2half2_rn(acc[i][j][0], acc[i][j][1]);
            if (row1 < M)
                *(__half2*)&C[(size_t)row1 * N + colb] =
                    __floats2half2_rn(acc[i][j][2], acc[i][j][3]);
        }
    }
}

// ---------------------- fused CSR aggregation ------------------------------
// out[c,:] = tanh( dinv[c]*( sum_r dinv[r]*h[r,:] + dinv[c]*h[c,:] ) + bias )
// h in fp16 (g_hh). One warp per node.

// Layer 1: D=256. Lane covers 8 cols. Output = tf32-rounded fp32 (GEMM2 input).
__global__ __launch_bounds__(256) void k_agg1(const float* __restrict__ bias, int n)
{
    int node = (int)((blockIdx.x * (unsigned)blockDim.x + threadIdx.x) >> 5);
    int lane = threadIdx.x & 31;
    if (node >= n) return;
    int base = lane * 8;

    float acc[8];
    #pragma unroll
    for (int k = 0; k < 8; k++) acc[k] = 0.f;

    int beg = g_start[node];
    int end = g_start[node + 1];

    int e = beg;
    for (; e + 2 <= end; e += 2) {
        int r0 = g_src[e];
        int r1 = g_src[e + 1];
        float w0 = __ldg(&g_dinv[r0]);
        float w1 = __ldg(&g_dinv[r1]);
        uint4 p0 = *(const uint4*)&g_hh[(size_t)r0 * D_H1 + base];
        uint4 p1 = *(const uint4*)&g_hh[(size_t)r1 * D_H1 + base];
        const __half2* q0 = (const __half2*)&p0;
        const __half2* q1 = (const __half2*)&p1;
        #pragma unroll
        for (int k = 0; k < 4; k++) {
            float2 f0 = __half22float2(q0[k]);
            float2 f1 = __half22float2(q1[k]);
            acc[2*k]   = fmaf(w0, f0.x, fmaf(w1, f1.x, acc[2*k]));
            acc[2*k+1] = fmaf(w0, f0.y, fmaf(w1, f1.y, acc[2*k+1]));
        }
    }
    if (e < end) {
        int r = g_src[e];
        float w = __ldg(&g_dinv[r]);
        uint4 p = *(const uint4*)&g_hh[(size_t)r * D_H1 + base];
        const __half2* q = (const __half2*)&p;
        #pragma unroll
        for (int k = 0; k < 4; k++) {
            float2 f = __half22float2(q[k]);
            acc[2*k]   = fmaf(w, f.x, acc[2*k]);
            acc[2*k+1] = fmaf(w, f.y, acc[2*k+1]);
        }
    }

    float dc = g_dinv[node];
    {   // self loop (weight dc)
        uint4 p = *(const uint4*)&g_hh[(size_t)node * D_H1 + base];
        const __half2* q = (const __half2*)&p;
        #pragma unroll
        for (int k = 0; k < 4; k++) {
            float2 f = __half22float2(q[k]);
            acc[2*k]   = fmaf(dc, f.x, acc[2*k]);
            acc[2*k+1] = fmaf(dc, f.y, acc[2*k+1]);
        }
    }

    float4 bv0 = *(const float4*)&bias[base];
    float4 bv1 = *(const float4*)&bias[base + 4];
    float4 o0, o1;
    o0.x = tf32f(fast_tanh(fmaf(dc, acc[0], bv0.x)));
    o0.y = tf32f(fast_tanh(fmaf(dc, acc[1], bv0.y)));
    o0.z = tf32f(fast_tanh(fmaf(dc, acc[2], bv0.z)));
    o0.w = tf32f(fast_tanh(fmaf(dc, acc[3], bv0.w)));
    o1.x = tf32f(fast_tanh(fmaf(dc, acc[4], bv1.x)));
    o1.y = tf32f(fast_tanh(fmaf(dc, acc[5], bv1.y)));
    o1.z = tf32f(fast_tanh(fmaf(dc, acc[6], bv1.z)));
    o1.w = tf32f(fast_tanh(fmaf(dc, acc[7], bv1.w)));
    *(float4*)&g_agg[(size_t)node * D_H1 + base] = o0;
    *(float4*)&g_agg[(size_t)node * D_H1 + base + 4] = o1;
}

// Layer 2: D=128. Lane covers 4 cols. Output fp32 outext.
__global__ __launch_bounds__(256) void k_agg2(
    const float* __restrict__ bias, float* __restrict__ out, int n)
{
    int node = (int)((blockIdx.x * (unsigned)blockDim.x + threadIdx.x) >> 5);
    int lane = threadIdx.x & 31;
    if (node >= n) return;
    int base = lane * 4;

    float acc[4];
    #pragma unroll
    for (int k = 0; k < 4; k++) acc[k] = 0.f;

    int beg = g_start[node];
    int end = g_start[node + 1];

    int e = beg;
    for (; e + 4 <= end; e += 4) {
        int r0 = g_src[e],     r1 = g_src[e + 1];
        int r2 = g_src[e + 2], r3 = g_src[e + 3];
        float w0 = __ldg(&g_dinv[r0]);
        float w1 = __ldg(&g_dinv[r1]);
        float w2 = __ldg(&g_dinv[r2]);
        float w3 = __ldg(&g_dinv[r3]);
        uint2 p0 = *(const uint2*)&g_hh[(size_t)r0 * D_H2 + base];
        uint2 p1 = *(const uint2*)&g_hh[(size_t)r1 * D_H2 + base];
        uint2 p2 = *(const uint2*)&g_hh[(size_t)r2 * D_H2 + base];
        uint2 p3 = *(const uint2*)&g_hh[(size_t)r3 * D_H2 + base];
        const __half2* q0 = (const __half2*)&p0;
        const __half2* q1 = (const __half2*)&p1;
        const __half2* q2 = (const __half2*)&p2;
        const __half2* q3 = (const __half2*)&p3;
        #pragma unroll
        for (int k = 0; k < 2; k++) {
            float2 f0 = __half22float2(q0[k]);
            float2 f1 = __half22float2(q1[k]);
            float2 f2 = __half22float2(q2[k]);
            float2 f3 = __half22float2(q3[k]);
            acc[2*k]   = fmaf(w0, f0.x, fmaf(w1, f1.x, fmaf(w2, f2.x, fmaf(w3, f3.x, acc[2*k]))));
            acc[2*k+1] = fmaf(w0, f0.y, fmaf(w1, f1.y, fmaf(w2, f2.y, fmaf(w3, f3.y, acc[2*k+1]))));
        }
    }
    for (; e < end; e++) {
        int r = g_src[e];
        float w = __ldg(&g_dinv[r]);
        uint2 p = *(const uint2*)&g_hh[(size_t)r * D_H2 + base];
        const __half2* q = (const __half2*)&p;
        #pragma unroll
        for (int k = 0; k < 2; k++) {
            float2 f = __half22float2(q[k]);
            acc[2*k]   = fmaf(w, f.x, acc[2*k]);
            acc[2*k+1] = fmaf(w, f.y, acc[2*k+1]);
        }
    }

    float dc = g_dinv[node];
    {
        uint2 p = *(const uint2*)&g_hh[(size_t)node * D_H2 + base];
        const __half2* q = (const __half2*)&p;
        #pragma unroll
        for (int k = 0; k < 2; k++) {
            float2 f = __half22float2(q[k]);
            acc[2*k]   = fmaf(dc, f.x, acc[2*k]);
            acc[2*k+1] = fmaf(dc, f.y, acc[2*k+1]);
        }
    }

    float4 bv = *(const float4*)&bias[base];
    float4 o;
    o.x = fast_tanh(fmaf(dc, acc[0], bv.x));
    o.y = fast_tanh(fmaf(dc, acc[1], bv.y));
    o.z = fast_tanh(fmaf(dc, acc[2], bv.z));
    o.w = fast_tanh(fmaf(dc, acc[3], bv.w));
    *(float4*)&out[(size_t)node * D_H2 + base] = o;
}

// ------------------------------ launch -------------------------------------

extern "C" void kernel_launch(void* const* d_in, const int* in_sizes, int n_in,
                              void* d_out, int out_size)
{
    const float* x   = (const float*)d_in[0];
    const int*   ei  = (const int*)d_in[1];     // int32 (JAX x64-disabled)
    const float* W1  = (const float*)d_in[2];
    const float* b1  = (const float*)d_in[3];
    const float* W2  = (const float*)d_in[4];
    const float* b2  = (const float*)d_in[5];
    float*       out = (float*)d_out;

    int n = in_sizes[0] / D_IN;       // 50000
    int E = in_sizes[1] / 2;          // 800000
    const int* row = ei;
    const int* col = ei + E;

    int nb = (n + SCAN_T - 1) / SCAN_T;   // scan blocks (196)

    // fork: full CSR chain on side stream, overlapping cvt + GEMM1
    cudaEventRecord(s_evFork, 0);
    cudaStreamWaitEvent(s_side, s_evFork, 0);
    k_deg_count<<<1024, 256, 0, s_side>>>(col, E);
    k_partial<<<nb, SCAN_T, 0, s_side>>>(n);
    k_scanpart<<<1, SCAN_T, 0, s_side>>>(nb);
    k_apply<<<nb, SCAN_T, 0, s_side>>>(n);
    k_csr_fill<<<1024, 256, 0, s_side>>>(row, col, E);
    cudaEventRecord(s_evJoin, s_side);

    // pre-convert x, W1, W2 to tf32 bits
    {
        int nx4 = n * D_IN / 4;
        int n14 = D_IN * D_H1 / 4;
        int n24 = D_H1 * D_H2 / 4;
        k_cvt3<<<2048, 256>>>(x, W1, W2, nx4, n14, n24);
    }

    {   // layer 1 GEMM: g_hh = fp16(x @ W1)
        dim3 grid((n + 127) / 128, D_H1 / 128);
        k_mma<1><<<grid, 256, MMA_SMEM_BYTES>>>(n, D_H1, D_IN);
    }

    cudaStreamWaitEvent(0, s_evJoin, 0);   // aggregate needs CSR + dinv

    // layer 1 aggregate: g_agg = tf32(tanh(...))  (GEMM2 input)
    k_agg1<<<(n * 32 + 255) / 256, 256>>>(b1, n);

    // layer 2 GEMM: g_hh = fp16(g_agg @ W2)
    {
        dim3 grid((n + 127) / 128, D_H2 / 128);
        k_mma<2><<<grid, 256, MMA_SMEM_BYTES>>>(n, D_H2, D_H1);
    }

    // layer 2 aggregate: out = tanh(...)
    k_agg2<<<(n * 32 + 255) / 256, 256>>>(b2, out, n);
}

// round 15
// speedup vs baseline: 2.2210x; 1.2615x over previous
#include <cuda_runtime.h>
#include <cuda_fp16.h>
#include <math.h>
#include <stdint.h>

// ---------------------------------------------------------------------------
// GCN 2-layer forward:
//   h1 = tanh( Anorm @ (x @ W1) + b1 )
//   h2 = tanh( Anorm @ (h1 @ W2) + b2 )
//
// R14: GEMM switched tf32 -> fp16 mma.m16n8k16 with ldmatrix fragment loads.
// fp16 has the SAME 10-bit mantissa as tf32 (identical rounding), but halves
// the mma instruction count and replaces 48 scalar LDS/chunk with 10 ldmatrix
// (R11-R13 showed the tf32 loop was issue/LDS-mix-bound, not latency-bound).
// Operands preconverted to fp16; agg1 emits fp16 directly. CSR + aggregates
// unchanged from R13.
//
// edge_index arrives as INT32 (JAX x64-disabled downcasts the int64 request).
// ---------------------------------------------------------------------------

#define NNODES_MAX 50000
#define NEDGES_MAX 800000
#define D_IN  256
#define D_H1  256
#define D_H2  128

__device__ __half g_hh[(size_t)NNODES_MAX * D_H1];  // fp16 GEMM output (h)
__device__ __half g_ah[(size_t)NNODES_MAX * D_H1];  // fp16 agg1 output (GEMM2 A)
__device__ __half g_xh[(size_t)NNODES_MAX * D_IN];  // fp16 copy of x
__device__ __half g_w1h[D_IN * D_H1];               // fp16 W1
__device__ __half g_w2h[D_H1 * D_H2];               // fp16 W2
__device__ float  g_dinv[NNODES_MAX];

__device__ int g_deg[NNODES_MAX];        // zero at load; re-zeroed by k_apply
__device__ int g_start[NNODES_MAX + 1];
__device__ int g_cursor[NNODES_MAX];
__device__ int g_src[NEDGES_MAX];

#define SCAN_T 256
#define SCAN_NB ((NNODES_MAX + SCAN_T - 1) / SCAN_T)   // 196
__device__ int g_part[SCAN_NB];
__device__ int g_partpref[SCAN_NB];

// GEMM tiling (fp16): block 128x128, BK=32, 4 stages.
#define A_STR_H 40               // 32 + 8 pad (halves): 80B row stride
#define B_STR_H 136              // 128 + 8 pad (halves): 272B row stride
#define STAGES 4
#define ASTAGE_H (128 * A_STR_H) // halves per A stage (10240B)
#define BSTAGE_H (32 * B_STR_H)  // halves per B stage (8704B)
#define MMA_SMEM_BYTES ((STAGES * (ASTAGE_H + BSTAGE_H)) * 2)   // 75776

template<int L> __global__ void k_mma(int M, int N, int K);

// Side stream + events + smem attribute (pre-main; no device allocations).
static cudaStream_t s_side = nullptr;
static cudaEvent_t  s_evFork = nullptr, s_evJoin = nullptr;
namespace {
struct StreamInit {
    StreamInit() {
        cudaStreamCreateWithFlags(&s_side, cudaStreamNonBlocking);
        cudaEventCreateWithFlags(&s_evFork, cudaEventDisableTiming);
        cudaEventCreateWithFlags(&s_evJoin, cudaEventDisableTiming);
        cudaFuncSetAttribute(k_mma<1>, cudaFuncAttributeMaxDynamicSharedMemorySize, MMA_SMEM_BYTES);
        cudaFuncSetAttribute(k_mma<2>, cudaFuncAttributeMaxDynamicSharedMemorySize, MMA_SMEM_BYTES);
    }
};
static StreamInit s_streamInit;
}

// ---------------------------- CSR build ------------------------------------

__global__ void k_deg_count(const int* __restrict__ col, int E) {
    int stride = gridDim.x * blockDim.x;
    for (int e = blockIdx.x * blockDim.x + threadIdx.x; e < E; e += stride)
        atomicAdd(&g_deg[col[e]], 1);
}

__global__ __launch_bounds__(SCAN_T) void k_partial(int n) {
    __shared__ int s[SCAN_T];
    int t = threadIdx.x;
    int i = blockIdx.x * SCAN_T + t;
    s[t] = (i < n) ? g_deg[i] : 0;
    __syncthreads();
    #pragma unroll
    for (int off = SCAN_T / 2; off > 0; off >>= 1) {
        if (t < off) s[t] += s[t + off];
        __syncthreads();
    }
    if (t == 0) g_part[blockIdx.x] = s[0];
}

__global__ __launch_bounds__(SCAN_T) void k_scanpart(int nb) {
    __shared__ int s[SCAN_T];
    int t = threadIdx.x;
    int my = (t < nb) ? g_part[t] : 0;
    s[t] = my;
    __syncthreads();
    #pragma unroll
    for (int off = 1; off < SCAN_T; off <<= 1) {
        int v = (t >= off) ? s[t - off] : 0;
        __syncthreads();
        s[t] += v;
        __syncthreads();
    }
    if (t < nb) g_partpref[t] = s[t] - my;   // exclusive
}

__global__ __launch_bounds__(SCAN_T) void k_apply(int n) {
    __shared__ int s[SCAN_T];
    int t = threadIdx.x;
    int i = blockIdx.x * SCAN_T + t;
    int d = (i < n) ? g_deg[i] : 0;
    s[t] = d;
    __syncthreads();
    #pragma unroll
    for (int off = 1; off < SCAN_T; off <<= 1) {
        int v = (t >= off) ? s[t - off] : 0;
        __syncthreads();
        s[t] += v;
        __syncthreads();
    }
    int ex = s[t] - d + g_partpref[blockIdx.x];
    if (i < n) {
        g_deg[i] = 0;                          // restore for next graph replay
        g_start[i] = ex;
        g_cursor[i] = ex;
        g_dinv[i] = rsqrtf((float)(d + 1));    // +1 self loop
        if (i == n - 1) g_start[n] = ex + d;
    }
}

__global__ void k_csr_fill(const int* __restrict__ row, const int* __restrict__ col, int E) {
    int stride = gridDim.x * blockDim.x;
    for (int e = blockIdx.x * blockDim.x + threadIdx.x; e < E; e += stride) {
        int slot = atomicAdd(&g_cursor[col[e]], 1);
        g_src[slot] = row[e];
    }
}

// --------------------------- math helpers ----------------------------------

__device__ __forceinline__ float fast_tanh(float x) {
    float ax = fabsf(x);
    float t, r;
    asm("ex2.approx.f32 %0, %1;" : "=f"(t) : "f"(ax * -2.885390081777927f)); // -2*log2(e)
    asm("rcp.approx.f32 %0, %1;" : "=f"(r) : "f"(1.0f + t));
    float y = fmaf(-2.0f * t, r, 1.0f);
    return copysignf(y, x);
}

__device__ __forceinline__ void mma_f16(
    float& c0, float& c1, float& c2, float& c3,
    uint32_t a0, uint32_t a1, uint32_t a2, uint32_t a3,
    uint32_t b0, uint32_t b1)
{
    asm volatile(
        "mma.sync.aligned.m16n8k16.row.col.f32.f16.f16.f32 "
        "{%0,%1,%2,%3}, {%4,%5,%6,%7}, {%8,%9}, {%0,%1,%2,%3};"
        : "+f"(c0), "+f"(c1), "+f"(c2), "+f"(c3)
        : "r"(a0), "r"(a1), "r"(a2), "r"(a3), "r"(b0), "r"(b1));
}

__device__ __forceinline__ void ldmat_x4(uint32_t& r0, uint32_t& r1,
                                         uint32_t& r2, uint32_t& r3, uint32_t addr)
{
    asm volatile("ldmatrix.sync.aligned.m8n8.x4.shared.b16 {%0,%1,%2,%3}, [%4];"
                 : "=r"(r0), "=r"(r1), "=r"(r2), "=r"(r3) : "r"(addr));
}
__device__ __forceinline__ void ldmat_x2t(uint32_t& r0, uint32_t& r1, uint32_t addr)
{
    asm volatile("ldmatrix.sync.aligned.m8n8.x2.trans.shared.b16 {%0,%1}, [%2];"
                 : "=r"(r0), "=r"(r1) : "r"(addr));
}

__device__ __forceinline__ void cp_async16(uint32_t smem_dst, const void* gsrc, bool pred) {
    int sz = pred ? 16 : 0;     // src-size 0 -> 16B zero-fill, no global read
    asm volatile("cp.async.cg.shared.global [%0], [%1], 16, %2;\n"
                 :: "r"(smem_dst), "l"(gsrc), "r"(sz) : "memory");
}
__device__ __forceinline__ void cp_async_commit() {
    asm volatile("cp.async.commit_group;\n" ::: "memory");
}
template<int N>
__device__ __forceinline__ void cp_async_wait() {
    asm volatile("cp.async.wait_group %0;\n" :: "n"(N) : "memory");
}

// -------------------------- pre-convert kernel ------------------------------
// fp32 -> fp16 for x, W1, W2. Grid-stride over float4 groups.

__global__ void k_cvt3(const float* __restrict__ x,
                       const float* __restrict__ w1,
                       const float* __restrict__ w2,
                       int nx4, int n14, int n24)
{
    int total = nx4 + n14 + n24;
    int stride = gridDim.x * blockDim.x;
    for (int i = blockIdx.x * blockDim.x + threadIdx.x; i < total; i += stride) {
        const float4* s; __half* d; int j;
        if (i < nx4)            { s = (const float4*)x;  d = g_xh;  j = i; }
        else if (i < nx4 + n14) { s = (const float4*)w1; d = g_w1h; j = i - nx4; }
        else                    { s = (const float4*)w2; d = g_w2h; j = i - nx4 - n14; }
        float4 v = s[j];
        __half2 h0 = __floats2half2_rn(v.x, v.y);
        __half2 h1 = __floats2half2_rn(v.z, v.w);
        *(uint2*)&d[(size_t)j * 4] = make_uint2(
            *(uint32_t*)&h0, *(uint32_t*)&h1);
    }
}

// -------------------------- tensor-core GEMM -------------------------------
// g_hh[M,N] (fp16) = A @ B, fp16 operands, f32 accumulate (m16n8k16+ldmatrix).
// L=1: A=g_xh, B=g_w1h.  L=2: A=g_ah, B=g_w2h.
// 4-stage cp.async pipeline; block 128x128, BK=32, 8 warps (4M x 2N).

template<int L>
__global__ __launch_bounds__(256, 2) void k_mma(int M, int N, int K)
{
    const __half* A = (L == 1) ? g_xh  : g_ah;
    const __half* B = (L == 1) ? g_w1h : g_w2h;
    __half* C = g_hh;

    extern __shared__ __half smem[];
    __half* As = smem;                        // [STAGES][ASTAGE_H]
    __half* Bs = smem + STAGES * ASTAGE_H;    // [STAGES][BSTAGE_H]
    uint32_t as_base = (uint32_t)__cvta_generic_to_shared(As);
    uint32_t bs_base = (uint32_t)__cvta_generic_to_shared(Bs);

    int tid  = threadIdx.x;
    int lane = tid & 31;
    int wid  = tid >> 5;
    int wm   = wid & 3;
    int wn   = wid >> 2;
    int bm   = blockIdx.x * 128;
    int bn   = blockIdx.y * 128;

    // cp.async staging coords (16B chunks)
    int f0 = tid * 2, f1 = tid * 2 + 1;
    int a_r0 = f0 >> 2,  a_c0 = (f0 & 3) * 8;    // halves
    int a_r1 = f1 >> 2,  a_c1 = (f1 & 3) * 8;
    int b_r0 = f0 >> 4,  b_c0 = (f0 & 15) * 8;
    int b_r1 = f1 >> 4,  b_c1 = (f1 & 15) * 8;

    // ldmatrix per-lane address offsets (bytes)
    // A x4: lane L -> mat = L>>3 (0..3): row += (mat&1)*8 + (L&7), col += (mat>>1)*8
    uint32_t laneA = (uint32_t)((((lane >> 3) & 1) * 8 + (lane & 7)) * A_STR_H
                                + (lane >> 4) * 8) * 2;
    // B x2.trans: lanes 0..15: row = (L>>3)*8 + (L&7) (lanes 16-31 ignored; wrap)
    uint32_t laneB = (uint32_t)((((lane >> 3) & 1) * 8 + (lane & 7)) * B_STR_H) * 2;

    float acc[2][8][4];
    #pragma unroll
    for (int i = 0; i < 2; i++)
        #pragma unroll
        for (int j = 0; j < 8; j++)
            #pragma unroll
            for (int v = 0; v < 4; v++) acc[i][j][v] = 0.0f;

    int lg = lane >> 2;
    int lq = lane & 3;

    auto issue_stage = [&](int stage, int kc) {
        uint32_t as = as_base + (uint32_t)(stage * ASTAGE_H) * 2;
        uint32_t bs = bs_base + (uint32_t)(stage * BSTAGE_H) * 2;
        int gr0 = bm + a_r0, gr1 = bm + a_r1;
        cp_async16(as + (a_r0 * A_STR_H + a_c0) * 2, &A[(size_t)gr0 * K + kc + a_c0], gr0 < M);
        cp_async16(as + (a_r1 * A_STR_H + a_c1) * 2, &A[(size_t)gr1 * K + kc + a_c1], gr1 < M);
        cp_async16(bs + (b_r0 * B_STR_H + b_c0) * 2, &B[(size_t)(kc + b_r0) * N + bn + b_c0], true);
        cp_async16(bs + (b_r1 * B_STR_H + b_c1) * 2, &B[(size_t)(kc + b_r1) * N + bn + b_c1], true);
        cp_async_commit();
    };

    auto compute = [&](int stage) {
        uint32_t as = as_base + (uint32_t)(stage * ASTAGE_H) * 2;
        uint32_t bs = bs_base + (uint32_t)(stage * BSTAGE_H) * 2;
        #pragma unroll
        for (int ks = 0; ks < 32; ks += 16) {
            uint32_t a[2][4];
            #pragma unroll
            for (int i = 0; i < 2; i++) {
                int r0 = wm * 32 + i * 16;
                ldmat_x4(a[i][0], a[i][1], a[i][2], a[i][3],
                         as + laneA + (uint32_t)(r0 * A_STR_H + ks) * 2);
            }
            #pragma unroll
            for (int j = 0; j < 8; j++) {
                int cb = wn * 64 + j * 8;
                uint32_t b0, b1;
                ldmat_x2t(b0, b1, bs + laneB + (uint32_t)(ks * B_STR_H + cb) * 2);
                #pragma unroll
                for (int i = 0; i < 2; i++)
                    mma_f16(acc[i][j][0], acc[i][j][1], acc[i][j][2], acc[i][j][3],
                            a[i][0], a[i][1], a[i][2], a[i][3], b0, b1);
            }
        }
    };

    int nk = K / 32;

    #pragma unroll
    for (int s = 0; s < STAGES - 1; s++) {
        if (s < nk) issue_stage(s, s * 32);
        else        cp_async_commit();
    }

    for (int c = 0; c < nk; c++) {
        cp_async_wait<STAGES - 2>();
        __syncthreads();
        int nl = c + STAGES - 1;
        if (nl < nk) issue_stage(nl % STAGES, nl * 32);
        else         cp_async_commit();
        compute(c % STAGES);
    }

    // epilogue: write fp16 (same acc layout as m16n8k8)
    #pragma unroll
    for (int i = 0; i < 2; i++) {
        int row0 = bm + wm * 32 + i * 16 + lg;
        int row1 = row0 + 8;
        #pragma unroll
        for (int j = 0; j < 8; j++) {
            int colb = bn + wn * 64 + j * 8 + 2 * lq;
            if (row0 < M)
                *(__half2*)&C[(size_t)row0 * N + colb] =
                    __floats2half2_rn(acc[i][j][0], acc[i][j][1]);
            if (row1 < M)
                *(__half2*)&C[(size_t)row1 * N + colb] =
                    __floats2half2_rn(acc[i][j][2], acc[i][j][3]);
        }
    }
}

// ---------------------- fused CSR aggregation ------------------------------
// out[c,:] = tanh( dinv[c]*( sum_r dinv[r]*h[r,:] + dinv[c]*h[c,:] ) + bias )
// h in fp16 (g_hh). One warp per node.

// Layer 1: D=256. Lane covers 8 cols. Output fp16 g_ah (GEMM2 input).
__global__ __launch_bounds__(256) void k_agg1(const float* __restrict__ bias, int n)
{
    int node = (int)((blockIdx.x * (unsigned)blockDim.x + threadIdx.x) >> 5);
    int lane = threadIdx.x & 31;
    if (node >= n) return;
    int base = lane * 8;

    float acc[8];
    #pragma unroll
    for (int k = 0; k < 8; k++) acc[k] = 0.f;

    int beg = g_start[node];
    int end = g_start[node + 1];

    int e = beg;
    for (; e + 2 <= end; e += 2) {
        int r0 = g_src[e];
        int r1 = g_src[e + 1];
        float w0 = __ldg(&g_dinv[r0]);
        float w1 = __ldg(&g_dinv[r1]);
        uint4 p0 = *(const uint4*)&g_hh[(size_t)r0 * D_H1 + base];
        uint4 p1 = *(const uint4*)&g_hh[(size_t)r1 * D_H1 + base];
        const __half2* q0 = (const __half2*)&p0;
        const __half2* q1 = (const __half2*)&p1;
        #pragma unroll
        for (int k = 0; k < 4; k++) {
            float2 fv0 = __half22float2(q0[k]);
            float2 fv1 = __half22float2(q1[k]);
            acc[2*k]   = fmaf(w0, fv0.x, fmaf(w1, fv1.x, acc[2*k]));
            acc[2*k+1] = fmaf(w0, fv0.y, fmaf(w1, fv1.y, acc[2*k+1]));
        }
    }
    if (e < end) {
        int r = g_src[e];
        float w = __ldg(&g_dinv[r]);
        uint4 p = *(const uint4*)&g_hh[(size_t)r * D_H1 + base];
        const __half2* q = (const __half2*)&p;
        #pragma unroll
        for (int k = 0; k < 4; k++) {
            float2 fv = __half22float2(q[k]);
            acc[2*k]   = fmaf(w, fv.x, acc[2*k]);
            acc[2*k+1] = fmaf(w, fv.y, acc[2*k+1]);
        }
    }

    float dc = g_dinv[node];
    {   // self loop (weight dc)
        uint4 p = *(const uint4*)&g_hh[(size_t)node * D_H1 + base];
        const __half2* q = (const __half2*)&p;
        #pragma unroll
        for (int k = 0; k < 4; k++) {
            float2 fv = __half22float2(q[k]);
            acc[2*k]   = fmaf(dc, fv.x, acc[2*k]);
            acc[2*k+1] = fmaf(dc, fv.y, acc[2*k+1]);
        }
    }

    float4 bv0 = *(const float4*)&bias[base];
    float4 bv1 = *(const float4*)&bias[base + 4];
    float o[8];
    o[0] = fast_tanh(fmaf(dc, acc[0], bv0.x));
    o[1] = fast_tanh(fmaf(dc, acc[1], bv0.y));
    o[2] = fast_tanh(fmaf(dc, acc[2], bv0.z));
    o[3] = fast_tanh(fmaf(dc, acc[3], bv0.w));
    o[4] = fast_tanh(fmaf(dc, acc[4], bv1.x));
    o[5] = fast_tanh(fmaf(dc, acc[5], bv1.y));
    o[6] = fast_tanh(fmaf(dc, acc[6], bv1.z));
    o[7] = fast_tanh(fmaf(dc, acc[7], bv1.w));
    __half2 h0 = __floats2half2_rn(o[0], o[1]);
    __half2 h1 = __floats2half2_rn(o[2], o[3]);
    __half2 h2 = __floats2half2_rn(o[4], o[5]);
    __half2 h3 = __floats2half2_rn(o[6], o[7]);
    *(uint4*)&g_ah[(size_t)node * D_H1 + base] = make_uint4(
        *(uint32_t*)&h0, *(uint32_t*)&h1, *(uint32_t*)&h2, *(uint32_t*)&h3);
}

// Layer 2: D=128. Lane covers 4 cols. Output fp32 outext.
__global__ __launch_bounds__(256) void k_agg2(
    const float* __restrict__ bias, float* __restrict__ out, int n)
{
    int node = (int)((blockIdx.x * (unsigned)blockDim.x + threadIdx.x) >> 5);
    int lane = threadIdx.x & 31;
    if (node >= n) return;
    int base = lane * 4;

    float acc[4];
    #pragma unroll
    for (int k = 0; k < 4; k++) acc[k] = 0.f;

    int beg = g_start[node];
    int end = g_start[node + 1];

    int e = beg;
    for (; e + 4 <= end; e += 4) {
        int r0 = g_src[e],     r1 = g_src[e + 1];
        int r2 = g_src[e + 2], r3 = g_src[e + 3];
        float w0 = __ldg(&g_dinv[r0]);
        float w1 = __ldg(&g_dinv[r1]);
        float w2 = __ldg(&g_dinv[r2]);
        float w3 = __ldg(&g_dinv[r3]);
        uint2 p0 = *(const uint2*)&g_hh[(size_t)r0 * D_H2 + base];
        uint2 p1 = *(const uint2*)&g_hh[(size_t)r1 * D_H2 + base];
        uint2 p2 = *(const uint2*)&g_hh[(size_t)r2 * D_H2 + base];
        uint2 p3 = *(const uint2*)&g_hh[(size_t)r3 * D_H2 + base];
        const __half2* q0 = (const __half2*)&p0;
        const __half2* q1 = (const __half2*)&p1;
        const __half2* q2 = (const __half2*)&p2;
        const __half2* q3 = (const __half2*)&p3;
        #pragma unroll
        for (int k = 0; k < 2; k++) {
            float2 fv0 = __half22float2(q0[k]);
            float2 fv1 = __half22float2(q1[k]);
            float2 fv2 = __half22float2(q2[k]);
            float2 fv3 = __half22float2(q3[k]);
            acc[2*k]   = fmaf(w0, fv0.x, fmaf(w1, fv1.x, fmaf(w2, fv2.x, fmaf(w3, fv3.x, acc[2*k]))));
            acc[2*k+1] = fmaf(w0, fv0.y, fmaf(w1, fv1.y, fmaf(w2, fv2.y, fmaf(w3, fv3.y, acc[2*k+1]))));
        }
    }
    for (; e < end; e++) {
        int r = g_src[e];
        float w = __ldg(&g_dinv[r]);
        uint2 p = *(const uint2*)&g_hh[(size_t)r * D_H2 + base];
        const __half2* q = (const __half2*)&p;
        #pragma unroll
        for (int k = 0; k < 2; k++) {
            float2 fv = __half22float2(q[k]);
            acc[2*k]   = fmaf(w, fv.x, acc[2*k]);
            acc[2*k+1] = fmaf(w, fv.y, acc[2*k+1]);
        }
    }

    float dc = g_dinv[node];
    {
        uint2 p = *(const uint2*)&g_hh[(size_t)node * D_H2 + base];
        const __half2* q = (const __half2*)&p;
        #pragma unroll
        for (int k = 0; k < 2; k++) {
            float2 fv = __half22float2(q[k]);
            acc[2*k]   = fmaf(dc, fv.x, acc[2*k]);
            acc[2*k+1] = fmaf(dc, fv.y, acc[2*k+1]);
        }
    }

    float4 bv = *(const float4*)&bias[base];
    float4 o;
    o.x = fast_tanh(fmaf(dc, acc[0], bv.x));
    o.y = fast_tanh(fmaf(dc, acc[1], bv.y));
    o.z = fast_tanh(fmaf(dc, acc[2], bv.z));
    o.w = fast_tanh(fmaf(dc, acc[3], bv.w));
    *(float4*)&out[(size_t)node * D_H2 + base] = o;
}

// ------------------------------ launch -------------------------------------

extern "C" void kernel_launch(void* const* d_in, const int* in_sizes, int n_in,
                              void* d_out, int out_size)
{
    const float* x   = (const float*)d_in[0];
    const int*   ei  = (const int*)d_in[1];     // int32 (JAX x64-disabled)
    const float* W1  = (const float*)d_in[2];
    const float* b1  = (const float*)d_in[3];
    const float* W2  = (const float*)d_in[4];
    const float* b2  = (const float*)d_in[5];
    float*       out = (float*)d_out;

    int n = in_sizes[0] / D_IN;       // 50000
    int E = in_sizes[1] / 2;          // 800000
    const int* row = ei;
    const int* col = ei + E;

    int nb = (n + SCAN_T - 1) / SCAN_T;   // scan blocks (196)

    // fork: full CSR chain on side stream, overlapping cvt + GEMM1
    cudaEventRecord(s_evFork, 0);
    cudaStreamWaitEvent(s_side, s_evFork, 0);
    k_deg_count<<<1024, 256, 0, s_side>>>(col, E);
    k_partial<<<nb, SCAN_T, 0, s_side>>>(n);
    k_scanpart<<<1, SCAN_T, 0, s_side>>>(nb);
    k_apply<<<nb, SCAN_T, 0, s_side>>>(n);
    k_csr_fill<<<1024, 256, 0, s_side>>>(row, col, E);
    cudaEventRecord(s_evJoin, s_side);

    // pre-convert x, W1, W2 to fp16
    {
        int nx4 = n * D_IN / 4;
        int n14 = D_IN * D_H1 / 4;
        int n24 = D_H1 * D_H2 / 4;
        k_cvt3<<<2048, 256>>>(x, W1, W2, nx4, n14, n24);
    }

    {   // layer 1 GEMM: g_hh = fp16(x @ W1)
        dim3 grid((n + 127) / 128, D_H1 / 128);
        k_mma<1><<<grid, 256, MMA_SMEM_BYTES>>>(n, D_H1, D_IN);
    }

    cudaStreamWaitEvent(0, s_evJoin, 0);   // aggregate needs CSR + dinv

    // layer 1 aggregate: g_ah = fp16(tanh(...))  (GEMM2 input)
    k_agg1<<<(n * 32 + 255) / 256, 256>>>(b1, n);

    // layer 2 GEMM: g_hh = fp16(g_ah @ W2)
    {
        dim3 grid((n + 127) / 128, D_H2 / 128);
        k_mma<2><<<grid, 256, MMA_SMEM_BYTES>>>(n, D_H2, D_H1);
    }

    // layer 2 aggregate: out = tanh(...)
    k_agg2<<<(n * 32 + 255) / 256, 256>>>(b2, out, n);
}